// round 13
// baseline (speedup 1.0000x reference)
#include <cuda_runtime.h>
#include <cuda_bf16.h>
#include <math.h>
#include <stdint.h>

#define VOCAB  50000
#define BATCH  1024
#define SEQ    120
#define EMBED  50
#define HIDDEN 300
#define NCLASS 5
#define GATES  1200   // 4*HIDDEN, packed as col' = 4*hh + gate (i,j,f,o)

// ---- LSTM scan geometry: M-split only, no inter-block communication ----
#define NBLK   64          // blocks; 16 batch rows each; all gates per block
#define BROWS  16
#define NSLICE 19          // k16 slices covering K=300 (pad to 304)
#define BSTR   16          // B n-row stride in elems (32B, 16B-aligned for LDSM)
#define SLICE_B 76800      // bytes per streamed slice (hi 38400 + lo 38400)
#define SLICE_V4 4800      // uint4 per slice
#define HALF_SLICE_E 19200 // bf16 elems per plane
#define HALF_SLICE_BYTES 38400
#define ASTR   328         // A image row stride in elems (656B, aligned)

// smem byte offsets
#define SMB_B   0                   // 2 slice buffers: 153600
#define SMB_AHI 153600              // 16*328*2 = 10496
#define SMB_ALO 164096              // 10496
#define SMB_C   174592              // 16*301*4 = 19264
#define SMB_IDS 193856              // 16*120*4 = 7680
#define SMEM_L  201536

// proj kernel
#define PROJ_ROWS 128
#define HSTRIDE 308
#define PROJ_SMEM ((PROJ_ROWS*HSTRIDE + HIDDEN*NCLASS + PROJ_ROWS*NCLASS + 8)*4)

typedef unsigned long long u64;

// ---------------- scratch ----------------
__device__ float EW_buf[(size_t)VOCAB * GATES];
__device__ float Hall_buf[(size_t)SEQ * BATCH * HIDDEN];
__device__ uint4 Wstream4[(size_t)NSLICE * SLICE_B / 16];  // bf16 hi/lo weight slices

// ---------------- helpers ----------------
__device__ __forceinline__ float sigf(float x) {
    return __fdividef(1.0f, 1.0f + __expf(-x));
}
__device__ __forceinline__ float tanhe(float x) {
    return 2.0f * __fdividef(1.0f, 1.0f + __expf(-2.0f * x)) - 1.0f;
}

__device__ __forceinline__ u64 pack2(float lo, float hi) {
    u64 r; asm("mov.b64 %0, {%1, %2};" : "=l"(r) : "f"(lo), "f"(hi)); return r;
}
__device__ __forceinline__ void unpack2(u64 v, float& lo, float& hi) {
    asm("mov.b64 {%0, %1}, %2;" : "=f"(lo), "=f"(hi) : "l"(v));
}
__device__ __forceinline__ u64 ffma2(u64 a, u64 b, u64 c) {
    u64 d; asm("fma.rn.f32x2 %0, %1, %2, %3;" : "=l"(d) : "l"(a), "l"(b), "l"(c));
    return d;
}
__device__ __forceinline__ uint32_t smem_u32(const void* p) {
    uint32_t a;
    asm("{ .reg .u64 t; cvta.to.shared.u64 t, %1; cvt.u32.u64 %0, t; }"
        : "=r"(a) : "l"(p));
    return a;
}

#define LDSM_X4(r, addr)                                                        \
    asm volatile("ldmatrix.sync.aligned.m8n8.x4.shared.b16 {%0,%1,%2,%3}, [%4];" \
        : "=r"((r)[0]), "=r"((r)[1]), "=r"((r)[2]), "=r"((r)[3]) : "r"(addr))
#define LDSM_X2(r, addr)                                                        \
    asm volatile("ldmatrix.sync.aligned.m8n8.x2.shared.b16 {%0,%1}, [%2];"      \
        : "=r"((r)[0]), "=r"((r)[1]) : "r"(addr))

__device__ __forceinline__ void mma_bf16(float* c, const uint32_t* a, const uint32_t* b) {
    asm volatile(
        "mma.sync.aligned.m16n8k16.row.col.f32.bf16.bf16.f32 "
        "{%0,%1,%2,%3}, {%4,%5,%6,%7}, {%8,%9}, {%0,%1,%2,%3};"
        : "+f"(c[0]), "+f"(c[1]), "+f"(c[2]), "+f"(c[3])
        : "r"(a[0]), "r"(a[1]), "r"(a[2]), "r"(a[3]), "r"(b[0]), "r"(b[1]));
}

#define CP_ASYNC16(dst, src) \
    asm volatile("cp.async.cg.shared.global [%0], [%1], 16;" :: "r"(dst), "l"(src))
#define CP_COMMIT()  asm volatile("cp.async.commit_group;" ::: "memory")
#define CP_WAIT1()   asm volatile("cp.async.wait_group 1;" ::: "memory")
#define CP_WAIT0()   asm volatile("cp.async.wait_group 0;" ::: "memory")

// ---------------------------------------------------------------------------
// EW[v][col'] = b_lstm[orig(col')] + sum_e emb[v][e] * W[e][orig(col')]
// (proven from R7)
// ---------------------------------------------------------------------------
__global__ __launch_bounds__(256) void ew_kernel(const float* __restrict__ emb,
                                                 const float* __restrict__ W,
                                                 const float* __restrict__ bl) {
    __shared__ float Ast[EMBED * 68];
    __shared__ float Bs[EMBED * 68];

    int tid = threadIdx.x;
    int tx = tid & 15, ty = tid >> 4;
    int rowBase = blockIdx.y * 64;
    int colBase = blockIdx.x * 64;

    for (int idx = tid; idx < 64 * EMBED; idx += 256) {
        int r = idx / EMBED, k = idx % EMBED;
        int v = rowBase + r;
        Ast[k * 68 + r] = (v < VOCAB) ? emb[(size_t)v * EMBED + k] : 0.f;
    }
    for (int idx = tid; idx < EMBED * 64; idx += 256) {
        int k = idx >> 6, c = idx & 63;
        int col = colBase + c;
        float val = 0.f;
        if (col < GATES) {
            int g = col & 3, hh = col >> 2;
            val = W[(size_t)k * GATES + g * HIDDEN + hh];
        }
        Bs[k * 68 + c] = val;
    }
    __syncthreads();

    u64 acc[2][4];
    #pragma unroll
    for (int p = 0; p < 2; p++)
        #pragma unroll
        for (int j = 0; j < 4; j++) acc[p][j] = 0ull;

    #pragma unroll 5
    for (int k = 0; k < EMBED; k++) {
        ulonglong2 A0 = *(const ulonglong2*)&Ast[k * 68 + ty * 4];
        float4 b4 = *(const float4*)&Bs[k * 68 + tx * 4];
        u64 bd0 = pack2(b4.x, b4.x), bd1 = pack2(b4.y, b4.y);
        u64 bd2 = pack2(b4.z, b4.z), bd3 = pack2(b4.w, b4.w);
        acc[0][0] = ffma2(A0.x, bd0, acc[0][0]);
        acc[0][1] = ffma2(A0.x, bd1, acc[0][1]);
        acc[0][2] = ffma2(A0.x, bd2, acc[0][2]);
        acc[0][3] = ffma2(A0.x, bd3, acc[0][3]);
        acc[1][0] = ffma2(A0.y, bd0, acc[1][0]);
        acc[1][1] = ffma2(A0.y, bd1, acc[1][1]);
        acc[1][2] = ffma2(A0.y, bd2, acc[1][2]);
        acc[1][3] = ffma2(A0.y, bd3, acc[1][3]);
    }

    int col0 = colBase + tx * 4;
    if (col0 < GATES) {
        int hh = col0 >> 2;
        float bias[4];
        #pragma unroll
        for (int j = 0; j < 4; j++) bias[j] = bl[j * HIDDEN + hh];
        #pragma unroll
        for (int p = 0; p < 2; p++) {
            float lo[4], hi[4];
            #pragma unroll
            for (int j = 0; j < 4; j++) unpack2(acc[p][j], lo[j], hi[j]);
            int v0 = rowBase + ty * 4 + p * 2;
            if (v0 < VOCAB) {
                float4 o = make_float4(lo[0] + bias[0], lo[1] + bias[1],
                                       lo[2] + bias[2], lo[3] + bias[3]);
                *(float4*)&EW_buf[(size_t)v0 * GATES + col0] = o;
            }
            if (v0 + 1 < VOCAB) {
                float4 o = make_float4(hi[0] + bias[0], hi[1] + bias[1],
                                       hi[2] + bias[2], hi[3] + bias[3]);
                *(float4*)&EW_buf[(size_t)(v0 + 1) * GATES + col0] = o;
            }
        }
    }
}

// ---------------------------------------------------------------------------
// Pack Whp into streamed bf16 hi/lo slices:
// Wstream[s][plane hi/lo][n 1200][kloc 16], k = s*16+kloc (k>=300 -> 0)
// ---------------------------------------------------------------------------
__global__ void pack_w(const float* __restrict__ W) {
    int idx = blockIdx.x * 256 + threadIdx.x;
    if (idx >= NSLICE * GATES * BSTR) return;
    int s = idx / (GATES * BSTR);
    int rem = idx % (GATES * BSTR);
    int n = rem / BSTR;
    int kl = rem % BSTR;
    int k = s * 16 + kl;
    float w = 0.f;
    if (k < HIDDEN) {
        int orig = (n & 3) * HIDDEN + (n >> 2);
        w = W[(size_t)(EMBED + k) * GATES + orig];
    }
    __nv_bfloat16 hi = __float2bfloat16_rn(w);
    __nv_bfloat16 lo = __float2bfloat16_rn(w - __bfloat162float(hi));
    __nv_bfloat16* base = (__nv_bfloat16*)Wstream4 + (size_t)s * (SLICE_B / 2);
    base[n * BSTR + kl] = hi;
    base[HALF_SLICE_E + n * BSTR + kl] = lo;
}

// ---------------------------------------------------------------------------
// Persistent LSTM scan: 64 independent blocks x 16 batch rows, all 1200 gates.
// h/c block-local in smem (h pre-split bf16 hi/lo for mma A); weight slices
// (bf16 hi/lo) cp.async-streamed from L2, double-buffered. 3-pass HMMA
// (Ahi*Bhi + Ahi*Blo + Alo*Bhi), fp32 accum. NO inter-block sync.
// ---------------------------------------------------------------------------
__global__ __launch_bounds__(256, 1) void lstm_persist(const int* __restrict__ ids) {
    extern __shared__ char smem[];
    const uint32_t smem_base = smem_u32(smem);
    const int tid = threadIdx.x;
    const int wid = tid >> 5;
    const int lane = tid & 31;
    const int rowBase = blockIdx.x * BROWS;

    float* Cs = (float*)(smem + SMB_C);        // [16][301]
    int* idsS = (int*)(smem + SMB_IDS);        // [16][120]

    // zero A hi/lo images (covers k-padding 300..327)
    for (int i = tid; i < (2 * BROWS * ASTR * 2) / 4; i += 256)
        ((uint32_t*)(smem + SMB_AHI))[i] = 0u;
    for (int i = tid; i < BROWS * SEQ; i += 256) {
        int r = i / SEQ, tt = i % SEQ;
        idsS[i] = ids[(size_t)(rowBase + r) * SEQ + tt];
    }
    __syncthreads();

    // lane-fixed epilogue constants (proven R11 fragment mapping)
    const int rloc = (lane >> 2) + ((lane & 1) << 3);   // 0..15
    const int grp = (lane & 3) >> 1;                    // unit within n8 tile
    const int b = rowBase + rloc;
    const int* idRow = &idsS[rloc * SEQ];

    // ldmatrix lane addr components (all 16B-aligned: ASTR*2=656, BSTR*2=32)
    const uint32_t aOff = ((lane & 15) * ASTR + ((lane >> 4) & 1) * 8) * 2;
    const uint32_t bLane = ((lane & 7) * BSTR + ((lane >> 3) & 1) * 8) * 2;

    for (int t = 0; t < SEQ; t++) {
        float acc[19][4];
        #pragma unroll
        for (int j = 0; j < 19; j++)
            #pragma unroll
            for (int q = 0; q < 4; q++) acc[j][q] = 0.f;

        if (t > 0) {
            // prologue: stream slice 0 into buffer 0
            {
                const char* gsrc = (const char*)Wstream4;
                uint32_t sdst = smem_base + SMB_B;
                #pragma unroll
                for (int j = 0; j < 19; j++) {
                    int idx = tid + j * 256;
                    if (idx < SLICE_V4) CP_ASYNC16(sdst + idx * 16, gsrc + (size_t)idx * 16);
                }
                CP_COMMIT();
            }
            for (int s = 0; s < NSLICE; s++) {
                if (s < NSLICE - 1) {
                    const char* gsrc = (const char*)Wstream4 + (size_t)(s + 1) * SLICE_B;
                    uint32_t sdst = smem_base + SMB_B + ((s + 1) & 1) * SLICE_B;
                    #pragma unroll
                    for (int j = 0; j < 19; j++) {
                        int idx = tid + j * 256;
                        if (idx < SLICE_V4) CP_ASYNC16(sdst + idx * 16, gsrc + (size_t)idx * 16);
                    }
                    CP_COMMIT();
                    CP_WAIT1();
                } else {
                    CP_WAIT0();
                }
                __syncthreads();

                // A fragments for this k16 slice (all warps broadcast-load)
                uint32_t ah[4], al[4];
                LDSM_X4(ah, smem_base + SMB_AHI + aOff + s * 32);  // s*16 elems *2B
                LDSM_X4(al, smem_base + SMB_ALO + aOff + s * 32);

                const uint32_t bufb = smem_base + SMB_B + (s & 1) * SLICE_B;
                #pragma unroll
                for (int j = 0; j < 19; j++) {
                    int T = wid + 8 * j;
                    if (T < 150) {
                        uint32_t boff = bufb + T * (8 * BSTR * 2) + bLane;
                        uint32_t bh[2], bl[2];
                        LDSM_X2(bh, boff);
                        LDSM_X2(bl, boff + HALF_SLICE_BYTES);
                        mma_bf16(acc[j], ah, bh);
                        mma_bf16(acc[j], ah, bl);
                        mma_bf16(acc[j], al, bh);
                    }
                }
                __syncthreads();
            }
        }

        // ---- fused gate epilogue: writes C (smem), Hall (fp32), A images ----
        {
            const int id = idRow[t];
            const size_t ewRow = (size_t)id * GATES;
            float* hallRow = &Hall_buf[((size_t)t * BATCH + b) * HIDDEN];
            #pragma unroll
            for (int j = 0; j < 19; j++) {
                int T = wid + 8 * j;
                if (T < 150) {
                    const float* c = acc[j];
                    u64 send = (lane & 1) ? pack2(c[0], c[1]) : pack2(c[2], c[3]);
                    u64 recv = __shfl_xor_sync(0xffffffffu, send, 1);
                    float r0, r1;
                    unpack2(recv, r0, r1);
                    float z0, z1, z2, z3;
                    if (!(lane & 1)) { z0 = c[0]; z1 = c[1]; z2 = r0; z3 = r1; }
                    else             { z0 = r0; z1 = r1; z2 = c[2]; z3 = c[3]; }
                    const int col4 = T * 8 + grp * 4;
                    const int u = col4 >> 2;              // hidden unit 0..299
                    float4 ew = *(const float4*)&EW_buf[ewRow + col4];
                    float zi = z0 + ew.x, zj = z1 + ew.y;
                    float zf = z2 + ew.z, zo = z3 + ew.w;
                    float cprev = (t == 0) ? 0.f : Cs[rloc * 301 + u];
                    float cn = cprev * sigf(zf + 1.0f) + sigf(zi) * tanhe(zj);
                    float hn = tanhe(cn) * sigf(zo);
                    Cs[rloc * 301 + u] = cn;
                    hallRow[u] = hn;
                    __nv_bfloat16 hhi = __float2bfloat16_rn(hn);
                    __nv_bfloat16 hlo = __float2bfloat16_rn(hn - __bfloat162float(hhi));
                    *(__nv_bfloat16*)(smem + SMB_AHI + (rloc * ASTR + u) * 2) = hhi;
                    *(__nv_bfloat16*)(smem + SMB_ALO + (rloc * ASTR + u) * 2) = hlo;
                }
            }
        }
        __syncthreads();   // A-image writes visible before next step's ldmatrix
    }
}

// ---------------------------------------------------------------------------
// out[row][c] = Hall[row] @ U + b2. (proven)
// ---------------------------------------------------------------------------
__global__ __launch_bounds__(256) void proj_kernel(const float* __restrict__ U,
                                                   const float* __restrict__ b2,
                                                   float* __restrict__ out) {
    extern __shared__ float psm[];
    float* Hs   = psm;                              // [128][308]
    float* Ut   = psm + PROJ_ROWS * HSTRIDE;        // [5][300]
    float* outS = Ut + HIDDEN * NCLASS;             // [128*5]
    float* b2s  = outS + PROJ_ROWS * NCLASS;

    const int tid = threadIdx.x;
    size_t rowBase = (size_t)blockIdx.x * PROJ_ROWS;
    const float* src = &Hall_buf[rowBase * HIDDEN];

    for (int i = tid; i < PROJ_ROWS * HIDDEN / 4; i += 256) {
        float4 v = *(const float4*)&src[i * 4];
        int r = (i * 4) / HIDDEN, hh = (i * 4) % HIDDEN;
        *(float4*)&Hs[r * HSTRIDE + hh] = v;
    }
    for (int i = tid; i < HIDDEN * NCLASS; i += 256) {
        int c = i / HIDDEN, hh = i % HIDDEN;
        Ut[i] = U[hh * NCLASS + c];
    }
    if (tid < NCLASS) b2s[tid] = b2[tid];
    __syncthreads();

    const int r = tid >> 1, half = tid & 1;
    const float* hrow = &Hs[r * HSTRIDE + half * 150];

    u64 acc[NCLASS];
    #pragma unroll
    for (int c = 0; c < NCLASS; c++) acc[c] = 0ull;
    #pragma unroll 5
    for (int i = 0; i < 75; i++) {
        u64 h2 = *(const u64*)&hrow[i * 2];
        #pragma unroll
        for (int c = 0; c < NCLASS; c++)
            acc[c] = ffma2(h2, *(const u64*)&Ut[c * HIDDEN + half * 150 + i * 2], acc[c]);
    }
    #pragma unroll
    for (int c = 0; c < NCLASS; c++) {
        float lo, hi;
        unpack2(acc[c], lo, hi);
        float s = lo + hi;
        s += __shfl_xor_sync(0xffffffffu, s, 1);
        if (half == 0) outS[r * NCLASS + c] = s + b2s[c];
    }
    __syncthreads();
    for (int i = tid; i < PROJ_ROWS * NCLASS; i += 256)
        out[rowBase * NCLASS + i] = outS[i];
}

// ---------------------------------------------------------------------------
extern "C" void kernel_launch(void* const* d_in, const int* in_sizes, int n_in,
                              void* d_out, int out_size) {
    const int*   ids = (const int*)d_in[0];     // (1024,120,1) int32
    const float* emb = (const float*)d_in[1];   // (50000,50)
    const float* W   = (const float*)d_in[2];   // (350,1200)
    const float* bl  = (const float*)d_in[3];   // (1200)
    const float* U   = (const float*)d_in[4];   // (300,5)
    const float* b2  = (const float*)d_in[5];   // (5)
    float* out = (float*)d_out;                 // (120,1024,5)

    cudaFuncSetAttribute(lstm_persist,
                         cudaFuncAttributeMaxDynamicSharedMemorySize, SMEM_L);
    cudaFuncSetAttribute(proj_kernel,
                         cudaFuncAttributeMaxDynamicSharedMemorySize, PROJ_SMEM);

    dim3 ewgrid((GATES + 63) / 64, (VOCAB + 63) / 64);
    ew_kernel<<<ewgrid, 256>>>(emb, W, bl);
    pack_w<<<(NSLICE * GATES * BSTR + 255) / 256, 256>>>(W);

    lstm_persist<<<NBLK, 256, SMEM_L>>>(ids);

    proj_kernel<<<(SEQ * BATCH) / PROJ_ROWS, 256, PROJ_SMEM>>>(U, b2, out);
}

// round 14
// speedup vs baseline: 1.1458x; 1.1458x over previous
#include <cuda_runtime.h>
#include <cuda_bf16.h>
#include <math.h>
#include <stdint.h>

#define VOCAB  50000
#define BATCH  1024
#define SEQ    120
#define EMBED  50
#define HIDDEN 300
#define NCLASS 5
#define GATES  1200   // 4*HIDDEN, packed as col' = 4*hh + gate (i,j,f,o)

// per-step kernel geometry (R11-proven block internals)
#define MT 8
#define NT 15
#define NBLK (MT*NT)       // 120 blocks
#define BM 128
#define BN 80              // 80 gate cols = 20 hidden units per tile
#define BSTRIDE 328        // B row stride (elems), conflict-free LDSM, 656B aligned
#define ASTRIDE_E 88       // A chunk row stride (elems), 176B... (16B aligned)
#define CHUNK_K 80         // 5 k16-steps per chunk, 4 chunks

// smem byte offsets
#define SMB_BHI 0
#define SMB_BLO 52480
#define SMB_AHI 104960
#define SMB_ALO 127488
#define SMEM_BYTES_L 150016

// proj kernel
#define PROJ_ROWS 128
#define HSTRIDE 308
#define PROJ_SMEM ((PROJ_ROWS*HSTRIDE + HIDDEN*NCLASS + PROJ_ROWS*NCLASS + 8)*4)

typedef unsigned long long u64;

// ---------------- scratch ----------------
__device__ float EW_buf[(size_t)VOCAB * GATES];
__device__ float Hall_buf[(size_t)SEQ * BATCH * HIDDEN];
__device__ float C_buf[BATCH * HIDDEN];
__device__ uint4 Bhi_g4[(NT * BN * BSTRIDE * 2) / 16];   // bf16 hi image
__device__ uint4 Blo_g4[(NT * BN * BSTRIDE * 2) / 16];   // bf16 lo image

// ---------------- helpers ----------------
__device__ __forceinline__ float sigf(float x) { return 1.0f / (1.0f + expf(-x)); }

__device__ __forceinline__ u64 pack2(float lo, float hi) {
    u64 r; asm("mov.b64 %0, {%1, %2};" : "=l"(r) : "f"(lo), "f"(hi)); return r;
}
__device__ __forceinline__ void unpack2(u64 v, float& lo, float& hi) {
    asm("mov.b64 {%0, %1}, %2;" : "=f"(lo), "=f"(hi) : "l"(v));
}
__device__ __forceinline__ u64 ffma2(u64 a, u64 b, u64 c) {
    u64 d; asm("fma.rn.f32x2 %0, %1, %2, %3;" : "=l"(d) : "l"(a), "l"(b), "l"(c));
    return d;
}
__device__ __forceinline__ uint32_t smem_u32(const void* p) {
    uint32_t a;
    asm("{ .reg .u64 t; cvta.to.shared.u64 t, %1; cvt.u32.u64 %0, t; }"
        : "=r"(a) : "l"(p));
    return a;
}

#define LDSM_X4(r, addr)                                                        \
    asm volatile("ldmatrix.sync.aligned.m8n8.x4.shared.b16 {%0,%1,%2,%3}, [%4];" \
        : "=r"((r)[0]), "=r"((r)[1]), "=r"((r)[2]), "=r"((r)[3]) : "r"(addr))
#define LDSM_X2(r, addr)                                                        \
    asm volatile("ldmatrix.sync.aligned.m8n8.x2.shared.b16 {%0,%1}, [%2];"      \
        : "=r"((r)[0]), "=r"((r)[1]) : "r"(addr))

__device__ __forceinline__ void mma_bf16(float* c, const uint32_t* a, const uint32_t* b) {
    asm volatile(
        "mma.sync.aligned.m16n8k16.row.col.f32.bf16.bf16.f32 "
        "{%0,%1,%2,%3}, {%4,%5,%6,%7}, {%8,%9}, {%0,%1,%2,%3};"
        : "+f"(c[0]), "+f"(c[1]), "+f"(c[2]), "+f"(c[3])
        : "r"(a[0]), "r"(a[1]), "r"(a[2]), "r"(a[3]), "r"(b[0]), "r"(b[1]));
}

// ---------------------------------------------------------------------------
// EW[v][col'] = b_lstm[orig(col')] + sum_e emb[v][e] * W[e][orig(col')]
// (proven)
// ---------------------------------------------------------------------------
__global__ __launch_bounds__(256) void ew_kernel(const float* __restrict__ emb,
                                                 const float* __restrict__ W,
                                                 const float* __restrict__ bl) {
    __shared__ float Ast[EMBED * 68];
    __shared__ float Bs[EMBED * 68];

    int tid = threadIdx.x;
    int tx = tid & 15, ty = tid >> 4;
    int rowBase = blockIdx.y * 64;
    int colBase = blockIdx.x * 64;

    for (int idx = tid; idx < 64 * EMBED; idx += 256) {
        int r = idx / EMBED, k = idx % EMBED;
        int v = rowBase + r;
        Ast[k * 68 + r] = (v < VOCAB) ? emb[(size_t)v * EMBED + k] : 0.f;
    }
    for (int idx = tid; idx < EMBED * 64; idx += 256) {
        int k = idx >> 6, c = idx & 63;
        int col = colBase + c;
        float val = 0.f;
        if (col < GATES) {
            int g = col & 3, hh = col >> 2;
            val = W[(size_t)k * GATES + g * HIDDEN + hh];
        }
        Bs[k * 68 + c] = val;
    }
    __syncthreads();

    u64 acc[2][4];
    #pragma unroll
    for (int p = 0; p < 2; p++)
        #pragma unroll
        for (int j = 0; j < 4; j++) acc[p][j] = 0ull;

    #pragma unroll 5
    for (int k = 0; k < EMBED; k++) {
        ulonglong2 A0 = *(const ulonglong2*)&Ast[k * 68 + ty * 4];
        float4 b4 = *(const float4*)&Bs[k * 68 + tx * 4];
        u64 bd0 = pack2(b4.x, b4.x), bd1 = pack2(b4.y, b4.y);
        u64 bd2 = pack2(b4.z, b4.z), bd3 = pack2(b4.w, b4.w);
        acc[0][0] = ffma2(A0.x, bd0, acc[0][0]);
        acc[0][1] = ffma2(A0.x, bd1, acc[0][1]);
        acc[0][2] = ffma2(A0.x, bd2, acc[0][2]);
        acc[0][3] = ffma2(A0.x, bd3, acc[0][3]);
        acc[1][0] = ffma2(A0.y, bd0, acc[1][0]);
        acc[1][1] = ffma2(A0.y, bd1, acc[1][1]);
        acc[1][2] = ffma2(A0.y, bd2, acc[1][2]);
        acc[1][3] = ffma2(A0.y, bd3, acc[1][3]);
    }

    int col0 = colBase + tx * 4;
    if (col0 < GATES) {
        int hh = col0 >> 2;
        float bias[4];
        #pragma unroll
        for (int j = 0; j < 4; j++) bias[j] = bl[j * HIDDEN + hh];
        #pragma unroll
        for (int p = 0; p < 2; p++) {
            float lo[4], hi[4];
            #pragma unroll
            for (int j = 0; j < 4; j++) unpack2(acc[p][j], lo[j], hi[j]);
            int v0 = rowBase + ty * 4 + p * 2;
            if (v0 < VOCAB) {
                float4 o = make_float4(lo[0] + bias[0], lo[1] + bias[1],
                                       lo[2] + bias[2], lo[3] + bias[3]);
                *(float4*)&EW_buf[(size_t)v0 * GATES + col0] = o;
            }
            if (v0 + 1 < VOCAB) {
                float4 o = make_float4(hi[0] + bias[0], hi[1] + bias[1],
                                       hi[2] + bias[2], hi[3] + bias[3]);
                *(float4*)&EW_buf[(size_t)(v0 + 1) * GATES + col0] = o;
            }
        }
    }
}

// ---------------------------------------------------------------------------
// Pack Whp into bf16 hi/lo B images: B[tile][n][k] = Whp[k][tile*80+n],
// [n][k] layout, k contiguous, row stride 328, zeros for k>=300. (proven)
// ---------------------------------------------------------------------------
__global__ void pack_b(const float* __restrict__ W) {
    int idx = blockIdx.x * 256 + threadIdx.x;
    if (idx >= NT * BN * BSTRIDE) return;
    int tile = idx / (BN * BSTRIDE);
    int rem  = idx % (BN * BSTRIDE);
    int n = rem / BSTRIDE;
    int k = rem % BSTRIDE;
    int col = tile * BN + n;
    int orig = (col & 3) * HIDDEN + (col >> 2);
    float w = (k < HIDDEN) ? W[(size_t)(EMBED + k) * GATES + orig] : 0.f;
    __nv_bfloat16 hi = __float2bfloat16_rn(w);
    __nv_bfloat16 lo = __float2bfloat16_rn(w - __bfloat162float(hi));
    ((__nv_bfloat16*)Bhi_g4)[idx] = hi;
    ((__nv_bfloat16*)Blo_g4)[idx] = lo;
}

// ---------------------------------------------------------------------------
// ONE LSTM step per launch (profile probe). R11-proven block internals:
// 120 blocks = 8 M-tiles(128 rows) x 15 N-tiles(80 gate cols); 8 warps =
// 4 m-groups x 2 n-groups, 2x5 m16n8 f32 frags per warp; bf16 hi/lo 3-pass
// HMMA; B tile copied from global each launch; A staged per 80-K chunk.
// ---------------------------------------------------------------------------
__global__ __launch_bounds__(256, 1) void step_kernel(int t, const int* __restrict__ ids) {
    extern __shared__ char smem[];
    const uint32_t smem_base = smem_u32(smem);
    const int tid = threadIdx.x;
    const int wid = tid >> 5;
    const int lane = tid & 31;
    const int wm = wid & 3;
    const int wn = wid >> 2;
    const int mt = blockIdx.x % MT;
    const int nt = blockIdx.x / MT;
    const int rowBase = mt * BM;
    const int colBase = nt * BN;

    // copy this tile's B images (per launch; ~97KB from L2)
    {
        const int nv = (BN * BSTRIDE * 2) / 16;   // 3280 uint4 per image
        const uint4* gH = &Bhi_g4[(size_t)nt * nv];
        const uint4* gL = &Blo_g4[(size_t)nt * nv];
        uint4* sH = (uint4*)(smem + SMB_BHI);
        uint4* sL = (uint4*)(smem + SMB_BLO);
        for (int i = tid; i < nv; i += 256) { sH[i] = gH[i]; sL[i] = gL[i]; }
    }

    const uint32_t aRow = wm * 32 + (lane & 15);
    const uint32_t aColOff = (lane >> 4) * 8;
    const uint32_t bRow = wn * 40 + (lane & 7);
    const uint32_t bColOff = ((lane >> 3) & 1) * 8;

    float acc[2][5][4];
    #pragma unroll
    for (int mi = 0; mi < 2; mi++)
        #pragma unroll
        for (int ni = 0; ni < 5; ni++)
            #pragma unroll
            for (int q = 0; q < 4; q++) acc[mi][ni][q] = 0.f;

    if (t > 0) {
        const float* hprev =
            &Hall_buf[(size_t)(t - 1) * BATCH * HIDDEN + (size_t)rowBase * HIDDEN];
        const int sr = tid >> 1, shalf = tid & 1;

        for (int cc = 0; cc < 4; cc++) {
            const int k0g = cc * CHUNK_K;
            __syncthreads();
            #pragma unroll
            for (int i = 0; i < 10; i++) {
                int k = shalf * 40 + i * 4;
                float4 v = make_float4(0.f, 0.f, 0.f, 0.f);
                if (k0g + k < HIDDEN)
                    v = *(const float4*)&hprev[(size_t)sr * HIDDEN + k0g + k];
                __nv_bfloat16 h0 = __float2bfloat16_rn(v.x);
                __nv_bfloat16 h1 = __float2bfloat16_rn(v.y);
                __nv_bfloat16 h2 = __float2bfloat16_rn(v.z);
                __nv_bfloat16 h3 = __float2bfloat16_rn(v.w);
                __nv_bfloat16 l0 = __float2bfloat16_rn(v.x - __bfloat162float(h0));
                __nv_bfloat16 l1 = __float2bfloat16_rn(v.y - __bfloat162float(h1));
                __nv_bfloat16 l2 = __float2bfloat16_rn(v.z - __bfloat162float(h2));
                __nv_bfloat16 l3 = __float2bfloat16_rn(v.w - __bfloat162float(h3));
                uint2 hv, lv;
                hv.x = ((uint32_t)__bfloat16_as_ushort(h1) << 16) | __bfloat16_as_ushort(h0);
                hv.y = ((uint32_t)__bfloat16_as_ushort(h3) << 16) | __bfloat16_as_ushort(h2);
                lv.x = ((uint32_t)__bfloat16_as_ushort(l1) << 16) | __bfloat16_as_ushort(l0);
                lv.y = ((uint32_t)__bfloat16_as_ushort(l3) << 16) | __bfloat16_as_ushort(l2);
                uint32_t off = (uint32_t)(sr * ASTRIDE_E + k) * 2;
                *(uint2*)(smem + SMB_AHI + off) = hv;
                *(uint2*)(smem + SMB_ALO + off) = lv;
            }
            __syncthreads();

            #pragma unroll
            for (int ks = 0; ks < 5; ks++) {
                const int kk = ks * 16;
                uint32_t ah[2][4], al[2][4];
                #pragma unroll
                for (int mi = 0; mi < 2; mi++) {
                    uint32_t off = ((aRow + mi * 16) * ASTRIDE_E + kk + aColOff) * 2;
                    LDSM_X4(ah[mi], smem_base + SMB_AHI + off);
                    LDSM_X4(al[mi], smem_base + SMB_ALO + off);
                }
                uint32_t bh[5][2], bl[5][2];
                #pragma unroll
                for (int ni = 0; ni < 5; ni++) {
                    uint32_t off = ((bRow + ni * 8) * BSTRIDE + k0g + kk + bColOff) * 2;
                    LDSM_X2(bh[ni], smem_base + SMB_BHI + off);
                    LDSM_X2(bl[ni], smem_base + SMB_BLO + off);
                }
                #pragma unroll
                for (int mi = 0; mi < 2; mi++)
                    #pragma unroll
                    for (int ni = 0; ni < 5; ni++) {
                        mma_bf16(acc[mi][ni], ah[mi], bh[ni]);
                        mma_bf16(acc[mi][ni], ah[mi], bl[ni]);
                        mma_bf16(acc[mi][ni], al[mi], bh[ni]);
                    }
            }
        }
    } else {
        __syncthreads();   // B copy visible (uniform path, harmless)
    }

    // ---- fused gate epilogue (proven R11 mapping) ----
    {
        const int rloc = (lane >> 2) + ((lane & 1) << 3);
        const int grp = (lane & 3) >> 1;
        #pragma unroll
        for (int mi = 0; mi < 2; mi++) {
            const int b = rowBase + wm * 32 + mi * 16 + rloc;
            const int id = __ldg(&ids[(size_t)b * SEQ + t]);
            const size_t ewRow = (size_t)id * GATES;
            float* hallRow = &Hall_buf[((size_t)t * BATCH + b) * HIDDEN];
            #pragma unroll
            for (int ni = 0; ni < 5; ni++) {
                const float* c = acc[mi][ni];
                u64 send = (lane & 1) ? pack2(c[0], c[1]) : pack2(c[2], c[3]);
                u64 recv = __shfl_xor_sync(0xffffffffu, send, 1);
                float r0, r1;
                unpack2(recv, r0, r1);
                float z0, z1, z2, z3;
                if (!(lane & 1)) { z0 = c[0]; z1 = c[1]; z2 = r0; z3 = r1; }
                else             { z0 = r0; z1 = r1; z2 = c[2]; z3 = c[3]; }
                const int col4 = colBase + wn * 40 + ni * 8 + grp * 4;
                const int hh = col4 >> 2;
                float4 ew = *(const float4*)&EW_buf[ewRow + col4];
                float zi = z0 + ew.x, zj = z1 + ew.y;
                float zf = z2 + ew.z, zo = z3 + ew.w;
                float cprev = (t == 0) ? 0.f : C_buf[b * HIDDEN + hh];
                float cn = cprev * sigf(zf + 1.0f) + sigf(zi) * tanhf(zj);
                float hn = tanhf(cn) * sigf(zo);
                C_buf[b * HIDDEN + hh] = cn;
                hallRow[hh] = hn;
            }
        }
    }
}

// ---------------------------------------------------------------------------
// out[row][c] = Hall[row] @ U + b2. (proven)
// ---------------------------------------------------------------------------
__global__ __launch_bounds__(256) void proj_kernel(const float* __restrict__ U,
                                                   const float* __restrict__ b2,
                                                   float* __restrict__ out) {
    extern __shared__ float psm[];
    float* Hs   = psm;                              // [128][308]
    float* Ut   = psm + PROJ_ROWS * HSTRIDE;        // [5][300]
    float* outS = Ut + HIDDEN * NCLASS;             // [128*5]
    float* b2s  = outS + PROJ_ROWS * NCLASS;

    const int tid = threadIdx.x;
    size_t rowBase = (size_t)blockIdx.x * PROJ_ROWS;
    const float* src = &Hall_buf[rowBase * HIDDEN];

    for (int i = tid; i < PROJ_ROWS * HIDDEN / 4; i += 256) {
        float4 v = *(const float4*)&src[i * 4];
        int r = (i * 4) / HIDDEN, hh = (i * 4) % HIDDEN;
        *(float4*)&Hs[r * HSTRIDE + hh] = v;
    }
    for (int i = tid; i < HIDDEN * NCLASS; i += 256) {
        int c = i / HIDDEN, hh = i % HIDDEN;
        Ut[i] = U[hh * NCLASS + c];
    }
    if (tid < NCLASS) b2s[tid] = b2[tid];
    __syncthreads();

    const int r = tid >> 1, half = tid & 1;
    const float* hrow = &Hs[r * HSTRIDE + half * 150];

    u64 acc[NCLASS];
    #pragma unroll
    for (int c = 0; c < NCLASS; c++) acc[c] = 0ull;
    #pragma unroll 5
    for (int i = 0; i < 75; i++) {
        u64 h2 = *(const u64*)&hrow[i * 2];
        #pragma unroll
        for (int c = 0; c < NCLASS; c++)
            acc[c] = ffma2(h2, *(const u64*)&Ut[c * HIDDEN + half * 150 + i * 2], acc[c]);
    }
    #pragma unroll
    for (int c = 0; c < NCLASS; c++) {
        float lo, hi;
        unpack2(acc[c], lo, hi);
        float s = lo + hi;
        s += __shfl_xor_sync(0xffffffffu, s, 1);
        if (half == 0) outS[r * NCLASS + c] = s + b2s[c];
    }
    __syncthreads();
    for (int i = tid; i < PROJ_ROWS * NCLASS; i += 256)
        out[rowBase * NCLASS + i] = outS[i];
}

// ---------------------------------------------------------------------------
extern "C" void kernel_launch(void* const* d_in, const int* in_sizes, int n_in,
                              void* d_out, int out_size) {
    const int*   ids = (const int*)d_in[0];     // (1024,120,1) int32
    const float* emb = (const float*)d_in[1];   // (50000,50)
    const float* W   = (const float*)d_in[2];   // (350,1200)
    const float* bl  = (const float*)d_in[3];   // (1200)
    const float* U   = (const float*)d_in[4];   // (300,5)
    const float* b2  = (const float*)d_in[5];   // (5)
    float* out = (float*)d_out;                 // (120,1024,5)

    cudaFuncSetAttribute(step_kernel,
                         cudaFuncAttributeMaxDynamicSharedMemorySize, SMEM_BYTES_L);
    cudaFuncSetAttribute(proj_kernel,
                         cudaFuncAttributeMaxDynamicSharedMemorySize, PROJ_SMEM);

    dim3 ewgrid((GATES + 63) / 64, (VOCAB + 63) / 64);
    ew_kernel<<<ewgrid, 256>>>(emb, W, bl);
    pack_b<<<(NT * BN * BSTRIDE + 255) / 256, 256>>>(W);

    for (int t = 0; t < SEQ; t++)
        step_kernel<<<NBLK, 256, SMEM_BYTES_L>>>(t, ids);

    proj_kernel<<<(SEQ * BATCH) / PROJ_ROWS, 256, PROJ_SMEM>>>(U, b2, out);
}

// round 15
// speedup vs baseline: 1.4745x; 1.2869x over previous
#include <cuda_runtime.h>
#include <cuda_bf16.h>
#include <math.h>
#include <stdint.h>

#define VOCAB  50000
#define BATCH  1024
#define SEQ    120
#define EMBED  50
#define HIDDEN 300
#define NCLASS 5
#define GATES  1200   // 4*HIDDEN, packed as col' = 4*hh + gate (i,j,f,o)

// per-step kernel geometry: BM=128 x BN=40, 240 blocks, 2 blocks/SM
#define MT 8
#define NTL 30
#define NBLK (MT*NTL)      // 240 blocks
#define BM 128
#define BN 40              // 40 gate cols = 10 hidden units per tile
#define BSTRIDE 328        // B row stride (elems), 656B (16B-aligned)
#define ASTR 88            // A chunk row stride (elems), 176B
#define CHUNK 80           // k elems per staged chunk (5 k16 steps, 4 chunks)
#define KP 320             // global H plane k-stride (pad 300..319 = 0)

// smem byte offsets
#define SMB_BHI 0                    // 40*328*2 = 26240
#define SMB_BLO 26240
#define SMB_AHI 52480                // 128*88*2 = 22528
#define SMB_ALO 75008
#define SMEM_STEP 97536              // < 113KB -> 2 blocks/SM

// proj kernel
#define PROJ_ROWS 128
#define HSTRIDE 308
#define PROJ_SMEM ((PROJ_ROWS*HSTRIDE + HIDDEN*NCLASS + PROJ_ROWS*NCLASS + 8)*4)

typedef unsigned long long u64;

// ---------------- scratch ----------------
__device__ float EW_buf[(size_t)VOCAB * GATES];
__device__ float Hall_buf[(size_t)SEQ * BATCH * HIDDEN];
__device__ float C_buf[BATCH * HIDDEN];
__device__ __nv_bfloat16 Hhi_buf[(size_t)SEQ * BATCH * KP];  // pre-split h hi (pad zeros)
__device__ __nv_bfloat16 Hlo_buf[(size_t)SEQ * BATCH * KP];  // pre-split h lo
__device__ uint4 Bhi_g4[(NTL * BN * BSTRIDE * 2) / 16];
__device__ uint4 Blo_g4[(NTL * BN * BSTRIDE * 2) / 16];

// ---------------- helpers ----------------
__device__ __forceinline__ float sigf(float x) {
    return __fdividef(1.0f, 1.0f + __expf(-x));
}
__device__ __forceinline__ float tanhe(float x) {
    return 2.0f * __fdividef(1.0f, 1.0f + __expf(-2.0f * x)) - 1.0f;
}

__device__ __forceinline__ u64 pack2(float lo, float hi) {
    u64 r; asm("mov.b64 %0, {%1, %2};" : "=l"(r) : "f"(lo), "f"(hi)); return r;
}
__device__ __forceinline__ void unpack2(u64 v, float& lo, float& hi) {
    asm("mov.b64 {%0, %1}, %2;" : "=f"(lo), "=f"(hi) : "l"(v));
}
__device__ __forceinline__ u64 ffma2(u64 a, u64 b, u64 c) {
    u64 d; asm("fma.rn.f32x2 %0, %1, %2, %3;" : "=l"(d) : "l"(a), "l"(b), "l"(c));
    return d;
}
__device__ __forceinline__ uint32_t smem_u32(const void* p) {
    uint32_t a;
    asm("{ .reg .u64 t; cvta.to.shared.u64 t, %1; cvt.u32.u64 %0, t; }"
        : "=r"(a) : "l"(p));
    return a;
}

#define LDSM_X4(r, addr)                                                        \
    asm volatile("ldmatrix.sync.aligned.m8n8.x4.shared.b16 {%0,%1,%2,%3}, [%4];" \
        : "=r"((r)[0]), "=r"((r)[1]), "=r"((r)[2]), "=r"((r)[3]) : "r"(addr))
#define LDSM_X2(r, addr)                                                        \
    asm volatile("ldmatrix.sync.aligned.m8n8.x2.shared.b16 {%0,%1}, [%2];"      \
        : "=r"((r)[0]), "=r"((r)[1]) : "r"(addr))

__device__ __forceinline__ void mma_bf16(float* c, const uint32_t* a, const uint32_t* b) {
    asm volatile(
        "mma.sync.aligned.m16n8k16.row.col.f32.bf16.bf16.f32 "
        "{%0,%1,%2,%3}, {%4,%5,%6,%7}, {%8,%9}, {%0,%1,%2,%3};"
        : "+f"(c[0]), "+f"(c[1]), "+f"(c[2]), "+f"(c[3])
        : "r"(a[0]), "r"(a[1]), "r"(a[2]), "r"(a[3]), "r"(b[0]), "r"(b[1]));
}

#define CP_ASYNC16(dst, src) \
    asm volatile("cp.async.cg.shared.global [%0], [%1], 16;" :: "r"(dst), "l"(src))
#define CP_COMMIT()  asm volatile("cp.async.commit_group;" ::: "memory")
#define CP_WAIT0()   asm volatile("cp.async.wait_group 0;" ::: "memory")

// ---------------------------------------------------------------------------
// EW[v][col'] = b_lstm[orig(col')] + sum_e emb[v][e] * W[e][orig(col')]
// (proven)
// ---------------------------------------------------------------------------
__global__ __launch_bounds__(256) void ew_kernel(const float* __restrict__ emb,
                                                 const float* __restrict__ W,
                                                 const float* __restrict__ bl) {
    __shared__ float Ast[EMBED * 68];
    __shared__ float Bs[EMBED * 68];

    int tid = threadIdx.x;
    int tx = tid & 15, ty = tid >> 4;
    int rowBase = blockIdx.y * 64;
    int colBase = blockIdx.x * 64;

    for (int idx = tid; idx < 64 * EMBED; idx += 256) {
        int r = idx / EMBED, k = idx % EMBED;
        int v = rowBase + r;
        Ast[k * 68 + r] = (v < VOCAB) ? emb[(size_t)v * EMBED + k] : 0.f;
    }
    for (int idx = tid; idx < EMBED * 64; idx += 256) {
        int k = idx >> 6, c = idx & 63;
        int col = colBase + c;
        float val = 0.f;
        if (col < GATES) {
            int g = col & 3, hh = col >> 2;
            val = W[(size_t)k * GATES + g * HIDDEN + hh];
        }
        Bs[k * 68 + c] = val;
    }
    __syncthreads();

    u64 acc[2][4];
    #pragma unroll
    for (int p = 0; p < 2; p++)
        #pragma unroll
        for (int j = 0; j < 4; j++) acc[p][j] = 0ull;

    #pragma unroll 5
    for (int k = 0; k < EMBED; k++) {
        ulonglong2 A0 = *(const ulonglong2*)&Ast[k * 68 + ty * 4];
        float4 b4 = *(const float4*)&Bs[k * 68 + tx * 4];
        u64 bd0 = pack2(b4.x, b4.x), bd1 = pack2(b4.y, b4.y);
        u64 bd2 = pack2(b4.z, b4.z), bd3 = pack2(b4.w, b4.w);
        acc[0][0] = ffma2(A0.x, bd0, acc[0][0]);
        acc[0][1] = ffma2(A0.x, bd1, acc[0][1]);
        acc[0][2] = ffma2(A0.x, bd2, acc[0][2]);
        acc[0][3] = ffma2(A0.x, bd3, acc[0][3]);
        acc[1][0] = ffma2(A0.y, bd0, acc[1][0]);
        acc[1][1] = ffma2(A0.y, bd1, acc[1][1]);
        acc[1][2] = ffma2(A0.y, bd2, acc[1][2]);
        acc[1][3] = ffma2(A0.y, bd3, acc[1][3]);
    }

    int col0 = colBase + tx * 4;
    if (col0 < GATES) {
        int hh = col0 >> 2;
        float bias[4];
        #pragma unroll
        for (int j = 0; j < 4; j++) bias[j] = bl[j * HIDDEN + hh];
        #pragma unroll
        for (int p = 0; p < 2; p++) {
            float lo[4], hi[4];
            #pragma unroll
            for (int j = 0; j < 4; j++) unpack2(acc[p][j], lo[j], hi[j]);
            int v0 = rowBase + ty * 4 + p * 2;
            if (v0 < VOCAB) {
                float4 o = make_float4(lo[0] + bias[0], lo[1] + bias[1],
                                       lo[2] + bias[2], lo[3] + bias[3]);
                *(float4*)&EW_buf[(size_t)v0 * GATES + col0] = o;
            }
            if (v0 + 1 < VOCAB) {
                float4 o = make_float4(hi[0] + bias[0], hi[1] + bias[1],
                                       hi[2] + bias[2], hi[3] + bias[3]);
                *(float4*)&EW_buf[(size_t)(v0 + 1) * GATES + col0] = o;
            }
        }
    }
}

// ---------------------------------------------------------------------------
// Pack Whp into bf16 hi/lo B images: B[tile][n][k] = Whp[k][tile*40+n].
// ---------------------------------------------------------------------------
__global__ void pack_b(const float* __restrict__ W) {
    int idx = blockIdx.x * 256 + threadIdx.x;
    if (idx >= NTL * BN * BSTRIDE) return;
    int tile = idx / (BN * BSTRIDE);
    int rem  = idx % (BN * BSTRIDE);
    int n = rem / BSTRIDE;
    int k = rem % BSTRIDE;
    int col = tile * BN + n;
    int orig = (col & 3) * HIDDEN + (col >> 2);
    float w = (k < HIDDEN) ? W[(size_t)(EMBED + k) * GATES + orig] : 0.f;
    __nv_bfloat16 hi = __float2bfloat16_rn(w);
    __nv_bfloat16 lo = __float2bfloat16_rn(w - __bfloat162float(hi));
    ((__nv_bfloat16*)Bhi_g4)[idx] = hi;
    ((__nv_bfloat16*)Blo_g4)[idx] = lo;
}

// ---------------------------------------------------------------------------
// ONE LSTM step per launch. 240 blocks = 8 M-tiles(128) x 30 N-tiles(40 cols),
// 2 blocks/SM. 8 warps = 8 m16 slices x full BN. A staged per 80-K chunk via
// cp.async from pre-split Hhi/Hlo planes (no converts). 3-pass bf16 HMMA.
// Epilogue writes C, Hall(fp32), and next step's Hhi/Hlo.
// ---------------------------------------------------------------------------
__global__ __launch_bounds__(256, 2) void step_kernel(int t, const int* __restrict__ ids) {
    extern __shared__ char smem[];
    const uint32_t smem_base = smem_u32(smem);
    const int tid = threadIdx.x;
    const int wid = tid >> 5;
    const int lane = tid & 31;
    const int mt = blockIdx.x % MT;
    const int nt = blockIdx.x / MT;
    const int rowBase = mt * BM;
    const int colBase = nt * BN;

    float acc[5][4];
    #pragma unroll
    for (int ni = 0; ni < 5; ni++)
        #pragma unroll
        for (int q = 0; q < 4; q++) acc[ni][q] = 0.f;

    if (t > 0) {
        // copy this tile's B images (52.5KB from L2)
        {
            const int nv = (BN * BSTRIDE * 2) / 16;   // 1640 uint4 per image
            const uint4* gH = &Bhi_g4[(size_t)nt * nv];
            const uint4* gL = &Blo_g4[(size_t)nt * nv];
            uint4* sH = (uint4*)(smem + SMB_BHI);
            uint4* sL = (uint4*)(smem + SMB_BLO);
            for (int i = tid; i < nv; i += 256) { sH[i] = gH[i]; sL[i] = gL[i]; }
        }

        const uint32_t aAddr = smem_base + SMB_AHI +
                               ((wid * 16 + (lane & 15)) * ASTR + (lane >> 4) * 8) * 2;
        const uint32_t bAddr = smem_base + SMB_BHI +
                               ((lane & 7) * BSTRIDE + ((lane >> 3) & 1) * 8) * 2;
        const size_t hbase = ((size_t)(t - 1) * BATCH + rowBase) * KP;

        for (int cc = 0; cc < 4; cc++) {
            const int k0 = cc * CHUNK;
            __syncthreads();   // prior chunk's ldmatrix reads done / B copy ordered
            // stage A chunk via cp.async: 128 rows x 80 k x 2 planes = 2560 x16B
            #pragma unroll
            for (int j = 0; j < 10; j++) {
                int idx = tid + j * 256;        // 0..2559
                int plane = idx >> 11;          // 0: hi (idx<1280? no, 2560/2=1280)
                int li = idx & 1279;            // only valid when split at 1280
                // recompute cleanly:
                plane = (idx < 1280) ? 0 : 1;
                li = (idx < 1280) ? idx : idx - 1280;
                int r = li / 10, kc = li % 10;
                const __nv_bfloat16* src = plane == 0
                    ? &Hhi_buf[hbase + (size_t)r * KP + k0 + kc * 8]
                    : &Hlo_buf[hbase + (size_t)r * KP + k0 + kc * 8];
                uint32_t dst = smem_base + (plane == 0 ? SMB_AHI : SMB_ALO)
                               + (r * ASTR + kc * 8) * 2;
                CP_ASYNC16(dst, src);
            }
            CP_COMMIT();
            CP_WAIT0();
            __syncthreads();

            #pragma unroll
            for (int ks = 0; ks < 5; ks++) {
                const int kk = ks * 16;
                uint32_t ah[4], al[4];
                LDSM_X4(ah, aAddr + kk * 2);
                LDSM_X4(al, aAddr + (ASTR * BM + kk) * 2);  // lo plane offset
                #pragma unroll
                for (int ni = 0; ni < 5; ni++) {
                    uint32_t boff = bAddr + (ni * 8 * BSTRIDE + k0 + kk) * 2;
                    uint32_t bh[2], bl[2];
                    LDSM_X2(bh, boff);
                    LDSM_X2(bl, boff + (SMB_BLO - SMB_BHI));
                    mma_bf16(acc[ni], ah, bh);
                    mma_bf16(acc[ni], ah, bl);
                    mma_bf16(acc[ni], al, bh);
                }
            }
        }
    }

    // ---- fused gate epilogue (R11-proven fragment mapping) ----
    {
        const int rloc = (lane >> 2) + ((lane & 1) << 3);
        const int grp = (lane & 3) >> 1;
        const int b = rowBase + wid * 16 + rloc;
        const int id = __ldg(&ids[(size_t)b * SEQ + t]);
        const size_t ewRow = (size_t)id * GATES;
        float* hallRow = &Hall_buf[((size_t)t * BATCH + b) * HIDDEN];
        __nv_bfloat16* hhiRow = &Hhi_buf[((size_t)t * BATCH + b) * KP];
        __nv_bfloat16* hloRow = &Hlo_buf[((size_t)t * BATCH + b) * KP];
        #pragma unroll
        for (int ni = 0; ni < 5; ni++) {
            const float* c = acc[ni];
            u64 send = (lane & 1) ? pack2(c[0], c[1]) : pack2(c[2], c[3]);
            u64 recv = __shfl_xor_sync(0xffffffffu, send, 1);
            float r0, r1;
            unpack2(recv, r0, r1);
            float z0, z1, z2, z3;
            if (!(lane & 1)) { z0 = c[0]; z1 = c[1]; z2 = r0; z3 = r1; }
            else             { z0 = r0; z1 = r1; z2 = c[2]; z3 = c[3]; }
            const int col4 = colBase + ni * 8 + grp * 4;
            const int hh = col4 >> 2;
            float4 ew = *(const float4*)&EW_buf[ewRow + col4];
            float zi = z0 + ew.x, zj = z1 + ew.y;
            float zf = z2 + ew.z, zo = z3 + ew.w;
            float cprev = (t == 0) ? 0.f : C_buf[b * HIDDEN + hh];
            float cn = cprev * sigf(zf + 1.0f) + sigf(zi) * tanhe(zj);
            float hn = tanhe(cn) * sigf(zo);
            C_buf[b * HIDDEN + hh] = cn;
            hallRow[hh] = hn;
            __nv_bfloat16 hhi = __float2bfloat16_rn(hn);
            hhiRow[hh] = hhi;
            hloRow[hh] = __float2bfloat16_rn(hn - __bfloat162float(hhi));
        }
    }
}

// ---------------------------------------------------------------------------
// out[row][c] = Hall[row] @ U + b2. (proven)
// ---------------------------------------------------------------------------
__global__ __launch_bounds__(256) void proj_kernel(const float* __restrict__ U,
                                                   const float* __restrict__ b2,
                                                   float* __restrict__ out) {
    extern __shared__ float psm[];
    float* Hs   = psm;                              // [128][308]
    float* Ut   = psm + PROJ_ROWS * HSTRIDE;        // [5][300]
    float* outS = Ut + HIDDEN * NCLASS;             // [128*5]
    float* b2s  = outS + PROJ_ROWS * NCLASS;

    const int tid = threadIdx.x;
    size_t rowBase = (size_t)blockIdx.x * PROJ_ROWS;
    const float* src = &Hall_buf[rowBase * HIDDEN];

    for (int i = tid; i < PROJ_ROWS * HIDDEN / 4; i += 256) {
        float4 v = *(const float4*)&src[i * 4];
        int r = (i * 4) / HIDDEN, hh = (i * 4) % HIDDEN;
        *(float4*)&Hs[r * HSTRIDE + hh] = v;
    }
    for (int i = tid; i < HIDDEN * NCLASS; i += 256) {
        int c = i / HIDDEN, hh = i % HIDDEN;
        Ut[i] = U[hh * NCLASS + c];
    }
    if (tid < NCLASS) b2s[tid] = b2[tid];
    __syncthreads();

    const int r = tid >> 1, half = tid & 1;
    const float* hrow = &Hs[r * HSTRIDE + half * 150];

    u64 acc[NCLASS];
    #pragma unroll
    for (int c = 0; c < NCLASS; c++) acc[c] = 0ull;
    #pragma unroll 5
    for (int i = 0; i < 75; i++) {
        u64 h2 = *(const u64*)&hrow[i * 2];
        #pragma unroll
        for (int c = 0; c < NCLASS; c++)
            acc[c] = ffma2(h2, *(const u64*)&Ut[c * HIDDEN + half * 150 + i * 2], acc[c]);
    }
    #pragma unroll
    for (int c = 0; c < NCLASS; c++) {
        float lo, hi;
        unpack2(acc[c], lo, hi);
        float s = lo + hi;
        s += __shfl_xor_sync(0xffffffffu, s, 1);
        if (half == 0) outS[r * NCLASS + c] = s + b2s[c];
    }
    __syncthreads();
    for (int i = tid; i < PROJ_ROWS * NCLASS; i += 256)
        out[rowBase * NCLASS + i] = outS[i];
}

// ---------------------------------------------------------------------------
extern "C" void kernel_launch(void* const* d_in, const int* in_sizes, int n_in,
                              void* d_out, int out_size) {
    const int*   ids = (const int*)d_in[0];     // (1024,120,1) int32
    const float* emb = (const float*)d_in[1];   // (50000,50)
    const float* W   = (const float*)d_in[2];   // (350,1200)
    const float* bl  = (const float*)d_in[3];   // (1200)
    const float* U   = (const float*)d_in[4];   // (300,5)
    const float* b2  = (const float*)d_in[5];   // (5)
    float* out = (float*)d_out;                 // (120,1024,5)

    cudaFuncSetAttribute(step_kernel,
                         cudaFuncAttributeMaxDynamicSharedMemorySize, SMEM_STEP);
    cudaFuncSetAttribute(proj_kernel,
                         cudaFuncAttributeMaxDynamicSharedMemorySize, PROJ_SMEM);

    dim3 ewgrid((GATES + 63) / 64, (VOCAB + 63) / 64);
    ew_kernel<<<ewgrid, 256>>>(emb, W, bl);
    pack_b<<<(NTL * BN * BSTRIDE + 255) / 256, 256>>>(W);

    for (int t = 0; t < SEQ; t++)
        step_kernel<<<NBLK, 256, SMEM_STEP>>>(t, ids);

    proj_kernel<<<(SEQ * BATCH) / PROJ_ROWS, 256, PROJ_SMEM>>>(U, b2, out);
}

// round 16
// speedup vs baseline: 1.6842x; 1.1422x over previous
#include <cuda_runtime.h>
#include <cuda_bf16.h>
#include <math.h>
#include <stdint.h>

#define VOCAB  50000
#define BATCH  1024
#define SEQ    120
#define EMBED  50
#define HIDDEN 300
#define NCLASS 5
#define GATES  1200   // 4*HIDDEN, packed as col' = 4*hh + gate (i,j,f,o)

// per-step kernel geometry: BM=128 x BN=40, 240 blocks, 2 blocks/SM
#define MT 8
#define NTL 30
#define NBLK (MT*NTL)      // 240 blocks
#define BM 128
#define BN 40              // 40 gate cols = 10 hidden units per tile
#define BSTRIDE 344        // B row stride (elems), 688B, bank-phase-spread
#define ASTR 56            // A chunk row stride (elems), 112B
#define CHUNK 48           // k elems per staged chunk (3 k16 steps)
#define NCH 7              // 7 chunks cover k in [0,336)
#define KP 336             // global H plane k-stride (pad 300..335 = 0)

// smem byte offsets
#define SMB_BHI 0                    // 40*344*2 = 27520
#define SMB_BLO 27520
#define SMB_A   55040                // 2 bufs x (hi 14336 + lo 14336) = 57344
#define A_PLANE 14336
#define A_BUF   28672
#define SMEM_STEP 112384             // <= 116224 -> 2 blocks/SM

// proj kernel
#define PROJ_ROWS 128
#define HSTRIDE 308
#define PROJ_SMEM ((PROJ_ROWS*HSTRIDE + HIDDEN*NCLASS + PROJ_ROWS*NCLASS + 8)*4)

typedef unsigned long long u64;

// ---------------- scratch ----------------
__device__ float EW_buf[(size_t)VOCAB * GATES];
__device__ float Hall_buf[(size_t)SEQ * BATCH * HIDDEN];
__device__ float C_buf[BATCH * HIDDEN];
__device__ __nv_bfloat16 Hhi_buf[(size_t)SEQ * BATCH * KP];  // pre-split h hi (pad zeros)
__device__ __nv_bfloat16 Hlo_buf[(size_t)SEQ * BATCH * KP];  // pre-split h lo
__device__ uint4 Bhi_g4[(NTL * BN * BSTRIDE * 2) / 16];
__device__ uint4 Blo_g4[(NTL * BN * BSTRIDE * 2) / 16];

// ---------------- helpers ----------------
__device__ __forceinline__ float sigf(float x) {
    return __fdividef(1.0f, 1.0f + __expf(-x));
}
__device__ __forceinline__ float tanhe(float x) {
    return 2.0f * __fdividef(1.0f, 1.0f + __expf(-2.0f * x)) - 1.0f;
}

__device__ __forceinline__ u64 pack2(float lo, float hi) {
    u64 r; asm("mov.b64 %0, {%1, %2};" : "=l"(r) : "f"(lo), "f"(hi)); return r;
}
__device__ __forceinline__ void unpack2(u64 v, float& lo, float& hi) {
    asm("mov.b64 {%0, %1}, %2;" : "=f"(lo), "=f"(hi) : "l"(v));
}
__device__ __forceinline__ u64 ffma2(u64 a, u64 b, u64 c) {
    u64 d; asm("fma.rn.f32x2 %0, %1, %2, %3;" : "=l"(d) : "l"(a), "l"(b), "l"(c));
    return d;
}
__device__ __forceinline__ uint32_t smem_u32(const void* p) {
    uint32_t a;
    asm("{ .reg .u64 t; cvta.to.shared.u64 t, %1; cvt.u32.u64 %0, t; }"
        : "=r"(a) : "l"(p));
    return a;
}

#define LDSM_X4(r, addr)                                                        \
    asm volatile("ldmatrix.sync.aligned.m8n8.x4.shared.b16 {%0,%1,%2,%3}, [%4];" \
        : "=r"((r)[0]), "=r"((r)[1]), "=r"((r)[2]), "=r"((r)[3]) : "r"(addr))
#define LDSM_X2(r, addr)                                                        \
    asm volatile("ldmatrix.sync.aligned.m8n8.x2.shared.b16 {%0,%1}, [%2];"      \
        : "=r"((r)[0]), "=r"((r)[1]) : "r"(addr))

__device__ __forceinline__ void mma_bf16(float* c, const uint32_t* a, const uint32_t* b) {
    asm volatile(
        "mma.sync.aligned.m16n8k16.row.col.f32.bf16.bf16.f32 "
        "{%0,%1,%2,%3}, {%4,%5,%6,%7}, {%8,%9}, {%0,%1,%2,%3};"
        : "+f"(c[0]), "+f"(c[1]), "+f"(c[2]), "+f"(c[3])
        : "r"(a[0]), "r"(a[1]), "r"(a[2]), "r"(a[3]), "r"(b[0]), "r"(b[1]));
}

#define CP_ASYNC16(dst, src) \
    asm volatile("cp.async.cg.shared.global [%0], [%1], 16;" :: "r"(dst), "l"(src))
#define CP_COMMIT()  asm volatile("cp.async.commit_group;" ::: "memory")
#define CP_WAIT1()   asm volatile("cp.async.wait_group 1;" ::: "memory")
#define CP_WAIT0()   asm volatile("cp.async.wait_group 0;" ::: "memory")

// ---------------------------------------------------------------------------
// EW[v][col'] = b_lstm[orig(col')] + sum_e emb[v][e] * W[e][orig(col')]
// (proven)
// ---------------------------------------------------------------------------
__global__ __launch_bounds__(256) void ew_kernel(const float* __restrict__ emb,
                                                 const float* __restrict__ W,
                                                 const float* __restrict__ bl) {
    __shared__ float Ast[EMBED * 68];
    __shared__ float Bs[EMBED * 68];

    int tid = threadIdx.x;
    int tx = tid & 15, ty = tid >> 4;
    int rowBase = blockIdx.y * 64;
    int colBase = blockIdx.x * 64;

    for (int idx = tid; idx < 64 * EMBED; idx += 256) {
        int r = idx / EMBED, k = idx % EMBED;
        int v = rowBase + r;
        Ast[k * 68 + r] = (v < VOCAB) ? emb[(size_t)v * EMBED + k] : 0.f;
    }
    for (int idx = tid; idx < EMBED * 64; idx += 256) {
        int k = idx >> 6, c = idx & 63;
        int col = colBase + c;
        float val = 0.f;
        if (col < GATES) {
            int g = col & 3, hh = col >> 2;
            val = W[(size_t)k * GATES + g * HIDDEN + hh];
        }
        Bs[k * 68 + c] = val;
    }
    __syncthreads();

    u64 acc[2][4];
    #pragma unroll
    for (int p = 0; p < 2; p++)
        #pragma unroll
        for (int j = 0; j < 4; j++) acc[p][j] = 0ull;

    #pragma unroll 5
    for (int k = 0; k < EMBED; k++) {
        ulonglong2 A0 = *(const ulonglong2*)&Ast[k * 68 + ty * 4];
        float4 b4 = *(const float4*)&Bs[k * 68 + tx * 4];
        u64 bd0 = pack2(b4.x, b4.x), bd1 = pack2(b4.y, b4.y);
        u64 bd2 = pack2(b4.z, b4.z), bd3 = pack2(b4.w, b4.w);
        acc[0][0] = ffma2(A0.x, bd0, acc[0][0]);
        acc[0][1] = ffma2(A0.x, bd1, acc[0][1]);
        acc[0][2] = ffma2(A0.x, bd2, acc[0][2]);
        acc[0][3] = ffma2(A0.x, bd3, acc[0][3]);
        acc[1][0] = ffma2(A0.y, bd0, acc[1][0]);
        acc[1][1] = ffma2(A0.y, bd1, acc[1][1]);
        acc[1][2] = ffma2(A0.y, bd2, acc[1][2]);
        acc[1][3] = ffma2(A0.y, bd3, acc[1][3]);
    }

    int col0 = colBase + tx * 4;
    if (col0 < GATES) {
        int hh = col0 >> 2;
        float bias[4];
        #pragma unroll
        for (int j = 0; j < 4; j++) bias[j] = bl[j * HIDDEN + hh];
        #pragma unroll
        for (int p = 0; p < 2; p++) {
            float lo[4], hi[4];
            #pragma unroll
            for (int j = 0; j < 4; j++) unpack2(acc[p][j], lo[j], hi[j]);
            int v0 = rowBase + ty * 4 + p * 2;
            if (v0 < VOCAB) {
                float4 o = make_float4(lo[0] + bias[0], lo[1] + bias[1],
                                       lo[2] + bias[2], lo[3] + bias[3]);
                *(float4*)&EW_buf[(size_t)v0 * GATES + col0] = o;
            }
            if (v0 + 1 < VOCAB) {
                float4 o = make_float4(hi[0] + bias[0], hi[1] + bias[1],
                                       hi[2] + bias[2], hi[3] + bias[3]);
                *(float4*)&EW_buf[(size_t)(v0 + 1) * GATES + col0] = o;
            }
        }
    }
}

// ---------------------------------------------------------------------------
// Pack Whp into bf16 hi/lo B images: B[tile][n][k] = Whp[k][tile*40+n].
// ---------------------------------------------------------------------------
__global__ void pack_b(const float* __restrict__ W) {
    int idx = blockIdx.x * 256 + threadIdx.x;
    if (idx >= NTL * BN * BSTRIDE) return;
    int tile = idx / (BN * BSTRIDE);
    int rem  = idx % (BN * BSTRIDE);
    int n = rem / BSTRIDE;
    int k = rem % BSTRIDE;
    int col = tile * BN + n;
    int orig = (col & 3) * HIDDEN + (col >> 2);
    float w = (k < HIDDEN) ? W[(size_t)(EMBED + k) * GATES + orig] : 0.f;
    __nv_bfloat16 hi = __float2bfloat16_rn(w);
    __nv_bfloat16 lo = __float2bfloat16_rn(w - __bfloat162float(hi));
    ((__nv_bfloat16*)Bhi_g4)[idx] = hi;
    ((__nv_bfloat16*)Blo_g4)[idx] = lo;
}

// ---------------------------------------------------------------------------
// ONE LSTM step per launch. 240 blocks = 8 M(128) x 30 N(40 cols), 2/SM.
// Software-pipelined: B + A-chunk0 in cp.async group 0, A double-buffered
// with per-chunk groups (wait_group 1 -> only chunk0 latency exposed).
// EW/C prefetched into registers before the GEMM. 3-pass bf16 HMMA.
// ---------------------------------------------------------------------------
__global__ __launch_bounds__(256, 2) void step_kernel(int t, const int* __restrict__ ids) {
    extern __shared__ char smem[];
    const uint32_t smem_base = smem_u32(smem);
    const int tid = threadIdx.x;
    const int wid = tid >> 5;
    const int lane = tid & 31;
    const int mt = blockIdx.x % MT;
    const int nt = blockIdx.x / MT;
    const int rowBase = mt * BM;
    const int colBase = nt * BN;

    // ---- epilogue prefetch: id known now; EW + cprev latency hidden ----
    const int rloc = (lane >> 2) + ((lane & 1) << 3);
    const int grp = (lane & 3) >> 1;
    const int b = rowBase + wid * 16 + rloc;
    const int id = __ldg(&ids[(size_t)b * SEQ + t]);
    const size_t ewRow = (size_t)id * GATES;
    float4 ewv[5];
    float cpv[5];
    #pragma unroll
    for (int ni = 0; ni < 5; ni++) {
        const int col4 = colBase + ni * 8 + grp * 4;
        ewv[ni] = *(const float4*)&EW_buf[ewRow + col4];
        cpv[ni] = (t > 0) ? C_buf[b * HIDDEN + (col4 >> 2)] : 0.f;
    }

    float acc[5][4];
    #pragma unroll
    for (int ni = 0; ni < 5; ni++)
        #pragma unroll
        for (int q = 0; q < 4; q++) acc[ni][q] = 0.f;

    if (t > 0) {
        const size_t hbase = ((size_t)(t - 1) * BATCH + rowBase) * KP;
        const char* hhiG = (const char*)&Hhi_buf[hbase];
        const char* hloG = (const char*)&Hlo_buf[hbase];

        // group 0: B images (3440 x16B) + A chunk 0
        {
            const int nv = (BN * BSTRIDE * 2) / 16;   // 1720 uint4 per image
            const char* gH = (const char*)&Bhi_g4[(size_t)nt * nv];
            const char* gL = (const char*)&Blo_g4[(size_t)nt * nv];
            for (int i = tid; i < nv; i += 256) {
                CP_ASYNC16(smem_base + SMB_BHI + i * 16, gH + (size_t)i * 16);
                CP_ASYNC16(smem_base + SMB_BLO + i * 16, gL + (size_t)i * 16);
            }
            // A chunk 0 -> buf 0 : 768 x16B per plane
            #pragma unroll
            for (int j = 0; j < 3; j++) {
                int li = tid + j * 256;   // 0..767
                int r = li / 6, kc = li % 6;
                uint32_t doff = (uint32_t)(r * ASTR + kc * 8) * 2;
                size_t soff = ((size_t)r * KP + kc * 8) * 2;
                CP_ASYNC16(smem_base + SMB_A + doff, hhiG + soff);
                CP_ASYNC16(smem_base + SMB_A + A_PLANE + doff, hloG + soff);
            }
            CP_COMMIT();
        }
        // group 1: A chunk 1 -> buf 1
        {
            #pragma unroll
            for (int j = 0; j < 3; j++) {
                int li = tid + j * 256;
                int r = li / 6, kc = li % 6;
                uint32_t doff = (uint32_t)(r * ASTR + kc * 8) * 2;
                size_t soff = ((size_t)r * KP + CHUNK + kc * 8) * 2;
                CP_ASYNC16(smem_base + SMB_A + A_BUF + doff, hhiG + soff);
                CP_ASYNC16(smem_base + SMB_A + A_BUF + A_PLANE + doff, hloG + soff);
            }
            CP_COMMIT();
        }

        const uint32_t aLane = ((wid * 16 + (lane & 15)) * ASTR + (lane >> 4) * 8) * 2;
        const uint32_t bAddr = smem_base + SMB_BHI +
                               ((lane & 7) * BSTRIDE + ((lane >> 3) & 1) * 8) * 2;

        for (int cc = 0; cc < NCH; cc++) {
            if (cc < NCH - 1) { CP_WAIT1(); } else { CP_WAIT0(); }
            __syncthreads();

            const uint32_t abuf = smem_base + SMB_A + (cc & 1) * A_BUF;
            const int k0 = cc * CHUNK;
            #pragma unroll
            for (int ks = 0; ks < 3; ks++) {
                const int kk = ks * 16;
                uint32_t ah[4], al[4];
                LDSM_X4(ah, abuf + aLane + kk * 2);
                LDSM_X4(al, abuf + A_PLANE + aLane + kk * 2);
                #pragma unroll
                for (int ni = 0; ni < 5; ni++) {
                    uint32_t boff = bAddr + (ni * 8 * BSTRIDE + k0 + kk) * 2;
                    uint32_t bh[2], bl[2];
                    LDSM_X2(bh, boff);
                    LDSM_X2(bl, boff + (SMB_BLO - SMB_BHI));
                    mma_bf16(acc[ni], ah, bh);
                    mma_bf16(acc[ni], ah, bl);
                    mma_bf16(acc[ni], al, bh);
                }
            }
            __syncthreads();
            if (cc < NCH - 2) {
                // issue chunk cc+2 into buf cc&1 (just-freed)
                const int kn = (cc + 2) * CHUNK;
                const uint32_t dbuf = smem_base + SMB_A + (cc & 1) * A_BUF;
                #pragma unroll
                for (int j = 0; j < 3; j++) {
                    int li = tid + j * 256;
                    int r = li / 6, kc = li % 6;
                    uint32_t doff = (uint32_t)(r * ASTR + kc * 8) * 2;
                    size_t soff = ((size_t)r * KP + kn + kc * 8) * 2;
                    CP_ASYNC16(dbuf + doff, hhiG + soff);
                    CP_ASYNC16(dbuf + A_PLANE + doff, hloG + soff);
                }
                CP_COMMIT();
            }
        }
    }

    // ---- fused gate epilogue (prefetched EW/C; proven fragment mapping) ----
    {
        float* hallRow = &Hall_buf[((size_t)t * BATCH + b) * HIDDEN];
        __nv_bfloat16* hhiRow = &Hhi_buf[((size_t)t * BATCH + b) * KP];
        __nv_bfloat16* hloRow = &Hlo_buf[((size_t)t * BATCH + b) * KP];
        #pragma unroll
        for (int ni = 0; ni < 5; ni++) {
            const float* c = acc[ni];
            u64 send = (lane & 1) ? pack2(c[0], c[1]) : pack2(c[2], c[3]);
            u64 recv = __shfl_xor_sync(0xffffffffu, send, 1);
            float r0, r1;
            unpack2(recv, r0, r1);
            float z0, z1, z2, z3;
            if (!(lane & 1)) { z0 = c[0]; z1 = c[1]; z2 = r0; z3 = r1; }
            else             { z0 = r0; z1 = r1; z2 = c[2]; z3 = c[3]; }
            const int col4 = colBase + ni * 8 + grp * 4;
            const int hh = col4 >> 2;
            float zi = z0 + ewv[ni].x, zj = z1 + ewv[ni].y;
            float zf = z2 + ewv[ni].z, zo = z3 + ewv[ni].w;
            float cn = cpv[ni] * sigf(zf + 1.0f) + sigf(zi) * tanhe(zj);
            float hn = tanhe(cn) * sigf(zo);
            C_buf[b * HIDDEN + hh] = cn;
            hallRow[hh] = hn;
            __nv_bfloat16 hhi = __float2bfloat16_rn(hn);
            hhiRow[hh] = hhi;
            hloRow[hh] = __float2bfloat16_rn(hn - __bfloat162float(hhi));
        }
    }
}

// ---------------------------------------------------------------------------
// out[row][c] = Hall[row] @ U + b2. (proven)
// ---------------------------------------------------------------------------
__global__ __launch_bounds__(256) void proj_kernel(const float* __restrict__ U,
                                                   const float* __restrict__ b2,
                                                   float* __restrict__ out) {
    extern __shared__ float psm[];
    float* Hs   = psm;                              // [128][308]
    float* Ut   = psm + PROJ_ROWS * HSTRIDE;        // [5][300]
    float* outS = Ut + HIDDEN * NCLASS;             // [128*5]
    float* b2s  = outS + PROJ_ROWS * NCLASS;

    const int tid = threadIdx.x;
    size_t rowBase = (size_t)blockIdx.x * PROJ_ROWS;
    const float* src = &Hall_buf[rowBase * HIDDEN];

    for (int i = tid; i < PROJ_ROWS * HIDDEN / 4; i += 256) {
        float4 v = *(const float4*)&src[i * 4];
        int r = (i * 4) / HIDDEN, hh = (i * 4) % HIDDEN;
        *(float4*)&Hs[r * HSTRIDE + hh] = v;
    }
    for (int i = tid; i < HIDDEN * NCLASS; i += 256) {
        int c = i / HIDDEN, hh = i % HIDDEN;
        Ut[i] = U[hh * NCLASS + c];
    }
    if (tid < NCLASS) b2s[tid] = b2[tid];
    __syncthreads();

    const int r = tid >> 1, half = tid & 1;
    const float* hrow = &Hs[r * HSTRIDE + half * 150];

    u64 acc[NCLASS];
    #pragma unroll
    for (int c = 0; c < NCLASS; c++) acc[c] = 0ull;
    #pragma unroll 5
    for (int i = 0; i < 75; i++) {
        u64 h2 = *(const u64*)&hrow[i * 2];
        #pragma unroll
        for (int c = 0; c < NCLASS; c++)
            acc[c] = ffma2(h2, *(const u64*)&Ut[c * HIDDEN + half * 150 + i * 2], acc[c]);
    }
    #pragma unroll
    for (int c = 0; c < NCLASS; c++) {
        float lo, hi;
        unpack2(acc[c], lo, hi);
        float s = lo + hi;
        s += __shfl_xor_sync(0xffffffffu, s, 1);
        if (half == 0) outS[r * NCLASS + c] = s + b2s[c];
    }
    __syncthreads();
    for (int i = tid; i < PROJ_ROWS * NCLASS; i += 256)
        out[rowBase * NCLASS + i] = outS[i];
}

// ---------------------------------------------------------------------------
extern "C" void kernel_launch(void* const* d_in, const int* in_sizes, int n_in,
                              void* d_out, int out_size) {
    const int*   ids = (const int*)d_in[0];     // (1024,120,1) int32
    const float* emb = (const float*)d_in[1];   // (50000,50)
    const float* W   = (const float*)d_in[2];   // (350,1200)
    const float* bl  = (const float*)d_in[3];   // (1200)
    const float* U   = (const float*)d_in[4];   // (300,5)
    const float* b2  = (const float*)d_in[5];   // (5)
    float* out = (float*)d_out;                 // (120,1024,5)

    cudaFuncSetAttribute(step_kernel,
                         cudaFuncAttributeMaxDynamicSharedMemorySize, SMEM_STEP);
    cudaFuncSetAttribute(proj_kernel,
                         cudaFuncAttributeMaxDynamicSharedMemorySize, PROJ_SMEM);

    dim3 ewgrid((GATES + 63) / 64, (VOCAB + 63) / 64);
    ew_kernel<<<ewgrid, 256>>>(emb, W, bl);
    pack_b<<<(NTL * BN * BSTRIDE + 255) / 256, 256>>>(W);

    for (int t = 0; t < SEQ; t++)
        step_kernel<<<NBLK, 256, SMEM_STEP>>>(t, ids);

    proj_kernel<<<(SEQ * BATCH) / PROJ_ROWS, 256, PROJ_SMEM>>>(U, b2, out);
}

// round 17
// speedup vs baseline: 1.7742x; 1.0534x over previous
#include <cuda_runtime.h>
#include <cuda_bf16.h>
#include <math.h>
#include <stdint.h>

#define VOCAB  50000
#define BATCH  1024
#define SEQ    120
#define EMBED  50
#define HIDDEN 300
#define NCLASS 5
#define GATES  1200   // 4*HIDDEN, packed as col' = 4*hh + gate (i,j,f,o)

// persistent scan geometry: BM=128 x BN=40, 240 blocks, 2 blocks/SM
#define MT 8
#define NTL 30
#define NBLK (MT*NTL)      // 240 blocks (<= 296 resident slots)
#define BM 128
#define BN 40              // 40 gate cols = 10 hidden units per tile
#define BSTRIDE 344        // B row stride (elems), 688B, bank-phase-spread
#define ASTR 56            // A chunk row stride (elems), 112B
#define CHUNK 48           // k elems per staged chunk (3 k16 steps)
#define NCH 7              // 7 chunks cover k in [0,336)
#define KP 336             // global H plane k-stride (pad 300..335 = 0)

// smem byte offsets
#define SMB_BHI 0                    // 40*344*2 = 27520
#define SMB_BLO 27520
#define SMB_A   55040                // 2 bufs x (hi 14336 + lo 14336) = 57344
#define A_PLANE 14336
#define A_BUF   28672
#define SMEM_STEP 112384             // 2 blocks/SM

// proj kernel
#define PROJ_ROWS 128
#define HSTRIDE 308
#define PROJ_SMEM ((PROJ_ROWS*HSTRIDE + HIDDEN*NCLASS + PROJ_ROWS*NCLASS + 8)*4)

typedef unsigned long long u64;

// ---------------- scratch ----------------
__device__ float EW_buf[(size_t)VOCAB * GATES];
__device__ float Hall_buf[(size_t)SEQ * BATCH * HIDDEN];
__device__ __nv_bfloat16 Hhi_buf[(size_t)SEQ * BATCH * KP];  // pre-split h hi (pad zeros)
__device__ __nv_bfloat16 Hlo_buf[(size_t)SEQ * BATCH * KP];  // pre-split h lo
__device__ uint4 Bhi_g4[(NTL * BN * BSTRIDE * 2) / 16];
__device__ uint4 Blo_g4[(NTL * BN * BSTRIDE * 2) / 16];

// per-mt barriers (proven R7 pattern; gen monotonic across graph replays)
__device__ unsigned bar_arrive[MT];
__device__ unsigned bar_gen[MT];

// ---------------- helpers ----------------
__device__ __forceinline__ unsigned ld_volatile_u32(unsigned* p) {
    unsigned v;
    asm volatile("ld.volatile.global.u32 %0, [%1];" : "=r"(v) : "l"(p));
    return v;
}
__device__ __forceinline__ float sigf(float x) {
    return __fdividef(1.0f, 1.0f + __expf(-x));
}
__device__ __forceinline__ float tanhe(float x) {
    return 2.0f * __fdividef(1.0f, 1.0f + __expf(-2.0f * x)) - 1.0f;
}

__device__ __forceinline__ u64 pack2(float lo, float hi) {
    u64 r; asm("mov.b64 %0, {%1, %2};" : "=l"(r) : "f"(lo), "f"(hi)); return r;
}
__device__ __forceinline__ void unpack2(u64 v, float& lo, float& hi) {
    asm("mov.b64 {%0, %1}, %2;" : "=f"(lo), "=f"(hi) : "l"(v));
}
__device__ __forceinline__ u64 ffma2(u64 a, u64 b, u64 c) {
    u64 d; asm("fma.rn.f32x2 %0, %1, %2, %3;" : "=l"(d) : "l"(a), "l"(b), "l"(c));
    return d;
}
__device__ __forceinline__ uint32_t smem_u32(const void* p) {
    uint32_t a;
    asm("{ .reg .u64 t; cvta.to.shared.u64 t, %1; cvt.u32.u64 %0, t; }"
        : "=r"(a) : "l"(p));
    return a;
}

#define LDSM_X4(r, addr)                                                        \
    asm volatile("ldmatrix.sync.aligned.m8n8.x4.shared.b16 {%0,%1,%2,%3}, [%4];" \
        : "=r"((r)[0]), "=r"((r)[1]), "=r"((r)[2]), "=r"((r)[3]) : "r"(addr))
#define LDSM_X2(r, addr)                                                        \
    asm volatile("ldmatrix.sync.aligned.m8n8.x2.shared.b16 {%0,%1}, [%2];"      \
        : "=r"((r)[0]), "=r"((r)[1]) : "r"(addr))

__device__ __forceinline__ void mma_bf16(float* c, const uint32_t* a, const uint32_t* b) {
    asm volatile(
        "mma.sync.aligned.m16n8k16.row.col.f32.bf16.bf16.f32 "
        "{%0,%1,%2,%3}, {%4,%5,%6,%7}, {%8,%9}, {%0,%1,%2,%3};"
        : "+f"(c[0]), "+f"(c[1]), "+f"(c[2]), "+f"(c[3])
        : "r"(a[0]), "r"(a[1]), "r"(a[2]), "r"(a[3]), "r"(b[0]), "r"(b[1]));
}

#define CP_ASYNC16(dst, src) \
    asm volatile("cp.async.cg.shared.global [%0], [%1], 16;" :: "r"(dst), "l"(src))
#define CP_COMMIT()  asm volatile("cp.async.commit_group;" ::: "memory")
#define CP_WAIT1()   asm volatile("cp.async.wait_group 1;" ::: "memory")
#define CP_WAIT0()   asm volatile("cp.async.wait_group 0;" ::: "memory")

// ---------------------------------------------------------------------------
// EW[v][col'] = b_lstm[orig(col')] + sum_e emb[v][e] * W[e][orig(col')]
// (proven)
// ---------------------------------------------------------------------------
__global__ __launch_bounds__(256) void ew_kernel(const float* __restrict__ emb,
                                                 const float* __restrict__ W,
                                                 const float* __restrict__ bl) {
    __shared__ float Ast[EMBED * 68];
    __shared__ float Bs[EMBED * 68];

    int tid = threadIdx.x;
    int tx = tid & 15, ty = tid >> 4;
    int rowBase = blockIdx.y * 64;
    int colBase = blockIdx.x * 64;

    for (int idx = tid; idx < 64 * EMBED; idx += 256) {
        int r = idx / EMBED, k = idx % EMBED;
        int v = rowBase + r;
        Ast[k * 68 + r] = (v < VOCAB) ? emb[(size_t)v * EMBED + k] : 0.f;
    }
    for (int idx = tid; idx < EMBED * 64; idx += 256) {
        int k = idx >> 6, c = idx & 63;
        int col = colBase + c;
        float val = 0.f;
        if (col < GATES) {
            int g = col & 3, hh = col >> 2;
            val = W[(size_t)k * GATES + g * HIDDEN + hh];
        }
        Bs[k * 68 + c] = val;
    }
    __syncthreads();

    u64 acc[2][4];
    #pragma unroll
    for (int p = 0; p < 2; p++)
        #pragma unroll
        for (int j = 0; j < 4; j++) acc[p][j] = 0ull;

    #pragma unroll 5
    for (int k = 0; k < EMBED; k++) {
        ulonglong2 A0 = *(const ulonglong2*)&Ast[k * 68 + ty * 4];
        float4 b4 = *(const float4*)&Bs[k * 68 + tx * 4];
        u64 bd0 = pack2(b4.x, b4.x), bd1 = pack2(b4.y, b4.y);
        u64 bd2 = pack2(b4.z, b4.z), bd3 = pack2(b4.w, b4.w);
        acc[0][0] = ffma2(A0.x, bd0, acc[0][0]);
        acc[0][1] = ffma2(A0.x, bd1, acc[0][1]);
        acc[0][2] = ffma2(A0.x, bd2, acc[0][2]);
        acc[0][3] = ffma2(A0.x, bd3, acc[0][3]);
        acc[1][0] = ffma2(A0.y, bd0, acc[1][0]);
        acc[1][1] = ffma2(A0.y, bd1, acc[1][1]);
        acc[1][2] = ffma2(A0.y, bd2, acc[1][2]);
        acc[1][3] = ffma2(A0.y, bd3, acc[1][3]);
    }

    int col0 = colBase + tx * 4;
    if (col0 < GATES) {
        int hh = col0 >> 2;
        float bias[4];
        #pragma unroll
        for (int j = 0; j < 4; j++) bias[j] = bl[j * HIDDEN + hh];
        #pragma unroll
        for (int p = 0; p < 2; p++) {
            float lo[4], hi[4];
            #pragma unroll
            for (int j = 0; j < 4; j++) unpack2(acc[p][j], lo[j], hi[j]);
            int v0 = rowBase + ty * 4 + p * 2;
            if (v0 < VOCAB) {
                float4 o = make_float4(lo[0] + bias[0], lo[1] + bias[1],
                                       lo[2] + bias[2], lo[3] + bias[3]);
                *(float4*)&EW_buf[(size_t)v0 * GATES + col0] = o;
            }
            if (v0 + 1 < VOCAB) {
                float4 o = make_float4(hi[0] + bias[0], hi[1] + bias[1],
                                       hi[2] + bias[2], hi[3] + bias[3]);
                *(float4*)&EW_buf[(size_t)(v0 + 1) * GATES + col0] = o;
            }
        }
    }
}

// ---------------------------------------------------------------------------
// Pack Whp into bf16 hi/lo B images: B[tile][n][k] = Whp[k][tile*40+n].
// ---------------------------------------------------------------------------
__global__ void pack_b(const float* __restrict__ W) {
    int idx = blockIdx.x * 256 + threadIdx.x;
    if (idx >= NTL * BN * BSTRIDE) return;
    int tile = idx / (BN * BSTRIDE);
    int rem  = idx % (BN * BSTRIDE);
    int n = rem / BSTRIDE;
    int k = rem % BSTRIDE;
    int col = tile * BN + n;
    int orig = (col & 3) * HIDDEN + (col >> 2);
    float w = (k < HIDDEN) ? W[(size_t)(EMBED + k) * GATES + orig] : 0.f;
    __nv_bfloat16 hi = __float2bfloat16_rn(w);
    __nv_bfloat16 lo = __float2bfloat16_rn(w - __bfloat162float(hi));
    ((__nv_bfloat16*)Bhi_g4)[idx] = hi;
    ((__nv_bfloat16*)Blo_g4)[idx] = lo;
}

// ---------------------------------------------------------------------------
// Persistent LSTM scan. 240 blocks = 8 mt x 30 nt, 2 blocks/SM (all resident).
// B hi/lo resident in smem for all 120 steps. A double-buffered cp.async
// pipeline from pre-split Hhi/Hlo planes. Cell state in REGISTERS (each
// thread owns its 5 (b,hh) cells every step). id prefetched one step ahead.
// Per-mt barrier (30 blocks) between steps.
// ---------------------------------------------------------------------------
__global__ __launch_bounds__(256, 2) void lstm_persist(const int* __restrict__ ids) {
    extern __shared__ char smem[];
    const uint32_t smem_base = smem_u32(smem);
    const int tid = threadIdx.x;
    const int wid = tid >> 5;
    const int lane = tid & 31;
    const int mt = blockIdx.x % MT;
    const int nt = blockIdx.x / MT;
    const int rowBase = mt * BM;
    const int colBase = nt * BN;

    // resident B copy (once)
    {
        const int nv = (BN * BSTRIDE * 2) / 16;   // 1720 uint4 per image
        const char* gH = (const char*)&Bhi_g4[(size_t)nt * nv];
        const char* gL = (const char*)&Blo_g4[(size_t)nt * nv];
        for (int i = tid; i < nv; i += 256) {
            CP_ASYNC16(smem_base + SMB_BHI + i * 16, gH + (size_t)i * 16);
            CP_ASYNC16(smem_base + SMB_BLO + i * 16, gL + (size_t)i * 16);
        }
        CP_COMMIT();
        CP_WAIT0();
    }
    __syncthreads();

    // lane-fixed epilogue constants (proven fragment mapping)
    const int rloc = (lane >> 2) + ((lane & 1) << 3);
    const int grp = (lane & 3) >> 1;
    const int b = rowBase + wid * 16 + rloc;
    const uint32_t aLane = ((wid * 16 + (lane & 15)) * ASTR + (lane >> 4) * 8) * 2;
    const uint32_t bAddr = smem_base + SMB_BHI +
                           ((lane & 7) * BSTRIDE + ((lane >> 3) & 1) * 8) * 2;

    float creg[5];
    #pragma unroll
    for (int ni = 0; ni < 5; ni++) creg[ni] = 0.f;

    int id_cur = __ldg(&ids[(size_t)b * SEQ]);

    for (int t = 0; t < SEQ; t++) {
        // EW prefetch (id known; overlaps with A chunk0 latency)
        const size_t ewRow = (size_t)id_cur * GATES;
        float4 ewv[5];
        #pragma unroll
        for (int ni = 0; ni < 5; ni++)
            ewv[ni] = *(const float4*)&EW_buf[ewRow + colBase + ni * 8 + grp * 4];

        float acc[5][4];
        #pragma unroll
        for (int ni = 0; ni < 5; ni++)
            #pragma unroll
            for (int q = 0; q < 4; q++) acc[ni][q] = 0.f;

        if (t > 0) {
            const size_t hbase = ((size_t)(t - 1) * BATCH + rowBase) * KP;
            const char* hhiG = (const char*)&Hhi_buf[hbase];
            const char* hloG = (const char*)&Hlo_buf[hbase];

            // groups 0,1: A chunks 0,1
            #pragma unroll
            for (int pre = 0; pre < 2; pre++) {
                const uint32_t dbuf = smem_base + SMB_A + pre * A_BUF;
                #pragma unroll
                for (int j = 0; j < 3; j++) {
                    int li = tid + j * 256;
                    int r = li / 6, kc = li % 6;
                    uint32_t doff = (uint32_t)(r * ASTR + kc * 8) * 2;
                    size_t soff = ((size_t)r * KP + pre * CHUNK + kc * 8) * 2;
                    CP_ASYNC16(dbuf + doff, hhiG + soff);
                    CP_ASYNC16(dbuf + A_PLANE + doff, hloG + soff);
                }
                CP_COMMIT();
            }

            for (int cc = 0; cc < NCH; cc++) {
                if (cc < NCH - 1) { CP_WAIT1(); } else { CP_WAIT0(); }
                __syncthreads();

                const uint32_t abuf = smem_base + SMB_A + (cc & 1) * A_BUF;
                const int k0 = cc * CHUNK;
                #pragma unroll
                for (int ks = 0; ks < 3; ks++) {
                    const int kk = ks * 16;
                    uint32_t ah[4], al[4];
                    LDSM_X4(ah, abuf + aLane + kk * 2);
                    LDSM_X4(al, abuf + A_PLANE + aLane + kk * 2);
                    #pragma unroll
                    for (int ni = 0; ni < 5; ni++) {
                        uint32_t boff = bAddr + (ni * 8 * BSTRIDE + k0 + kk) * 2;
                        uint32_t bh[2], bl[2];
                        LDSM_X2(bh, boff);
                        LDSM_X2(bl, boff + (SMB_BLO - SMB_BHI));
                        mma_bf16(acc[ni], ah, bh);
                        mma_bf16(acc[ni], ah, bl);
                        mma_bf16(acc[ni], al, bh);
                    }
                }
                __syncthreads();
                if (cc < NCH - 2) {
                    const int kn = (cc + 2) * CHUNK;
                    const uint32_t dbuf = smem_base + SMB_A + (cc & 1) * A_BUF;
                    #pragma unroll
                    for (int j = 0; j < 3; j++) {
                        int li = tid + j * 256;
                        int r = li / 6, kc = li % 6;
                        uint32_t doff = (uint32_t)(r * ASTR + kc * 8) * 2;
                        size_t soff = ((size_t)r * KP + kn + kc * 8) * 2;
                        CP_ASYNC16(dbuf + doff, hhiG + soff);
                        CP_ASYNC16(dbuf + A_PLANE + doff, hloG + soff);
                    }
                    CP_COMMIT();
                }
            }
        }

        // prefetch next step's id (consumed next iteration; long slack)
        if (t + 1 < SEQ) id_cur = __ldg(&ids[(size_t)b * SEQ + t + 1]);

        // ---- fused gate epilogue: cell state in registers ----
        {
            float* hallRow = &Hall_buf[((size_t)t * BATCH + b) * HIDDEN];
            __nv_bfloat16* hhiRow = &Hhi_buf[((size_t)t * BATCH + b) * KP];
            __nv_bfloat16* hloRow = &Hlo_buf[((size_t)t * BATCH + b) * KP];
            #pragma unroll
            for (int ni = 0; ni < 5; ni++) {
                const float* c = acc[ni];
                u64 send = (lane & 1) ? pack2(c[0], c[1]) : pack2(c[2], c[3]);
                u64 recv = __shfl_xor_sync(0xffffffffu, send, 1);
                float r0, r1;
                unpack2(recv, r0, r1);
                float z0, z1, z2, z3;
                if (!(lane & 1)) { z0 = c[0]; z1 = c[1]; z2 = r0; z3 = r1; }
                else             { z0 = r0; z1 = r1; z2 = c[2]; z3 = c[3]; }
                const int col4 = colBase + ni * 8 + grp * 4;
                const int hh = col4 >> 2;
                float zi = z0 + ewv[ni].x, zj = z1 + ewv[ni].y;
                float zf = z2 + ewv[ni].z, zo = z3 + ewv[ni].w;
                float cn = creg[ni] * sigf(zf + 1.0f) + sigf(zi) * tanhe(zj);
                float hn = tanhe(cn) * sigf(zo);
                creg[ni] = cn;
                hallRow[hh] = hn;
                __nv_bfloat16 hhi = __float2bfloat16_rn(hn);
                hhiRow[hh] = hhi;
                hloRow[hh] = __float2bfloat16_rn(hn - __bfloat162float(hhi));
            }
        }

        // ---- per-mt barrier (30 blocks share mt; proven pattern) ----
        if (t < SEQ - 1) {
            __threadfence();
            __syncthreads();
            if (tid == 0) {
                unsigned gen = ld_volatile_u32(&bar_gen[mt]);
                if (atomicAdd(&bar_arrive[mt], 1u) == NTL - 1) {
                    atomicExch(&bar_arrive[mt], 0u);
                    __threadfence();
                    atomicExch(&bar_gen[mt], gen + 1);
                } else {
                    int spins = 0;
                    while (ld_volatile_u32(&bar_gen[mt]) == gen) {
                        if (++spins > 16) __nanosleep(128);
                    }
                }
                __threadfence();
            }
            __syncthreads();
        }
    }
}

// ---------------------------------------------------------------------------
// out[row][c] = Hall[row] @ U + b2. (proven)
// ---------------------------------------------------------------------------
__global__ __launch_bounds__(256) void proj_kernel(const float* __restrict__ U,
                                                   const float* __restrict__ b2,
                                                   float* __restrict__ out) {
    extern __shared__ float psm[];
    float* Hs   = psm;                              // [128][308]
    float* Ut   = psm + PROJ_ROWS * HSTRIDE;        // [5][300]
    float* outS = Ut + HIDDEN * NCLASS;             // [128*5]
    float* b2s  = outS + PROJ_ROWS * NCLASS;

    const int tid = threadIdx.x;
    size_t rowBase = (size_t)blockIdx.x * PROJ_ROWS;
    const float* src = &Hall_buf[rowBase * HIDDEN];

    for (int i = tid; i < PROJ_ROWS * HIDDEN / 4; i += 256) {
        float4 v = *(const float4*)&src[i * 4];
        int r = (i * 4) / HIDDEN, hh = (i * 4) % HIDDEN;
        *(float4*)&Hs[r * HSTRIDE + hh] = v;
    }
    for (int i = tid; i < HIDDEN * NCLASS; i += 256) {
        int c = i / HIDDEN, hh = i % HIDDEN;
        Ut[i] = U[hh * NCLASS + c];
    }
    if (tid < NCLASS) b2s[tid] = b2[tid];
    __syncthreads();

    const int r = tid >> 1, half = tid & 1;
    const float* hrow = &Hs[r * HSTRIDE + half * 150];

    u64 acc[NCLASS];
    #pragma unroll
    for (int c = 0; c < NCLASS; c++) acc[c] = 0ull;
    #pragma unroll 5
    for (int i = 0; i < 75; i++) {
        u64 h2 = *(const u64*)&hrow[i * 2];
        #pragma unroll
        for (int c = 0; c < NCLASS; c++)
            acc[c] = ffma2(h2, *(const u64*)&Ut[c * HIDDEN + half * 150 + i * 2], acc[c]);
    }
    #pragma unroll
    for (int c = 0; c < NCLASS; c++) {
        float lo, hi;
        unpack2(acc[c], lo, hi);
        float s = lo + hi;
        s += __shfl_xor_sync(0xffffffffu, s, 1);
        if (half == 0) outS[r * NCLASS + c] = s + b2s[c];
    }
    __syncthreads();
    for (int i = tid; i < PROJ_ROWS * NCLASS; i += 256)
        out[rowBase * NCLASS + i] = outS[i];
}

// ---------------------------------------------------------------------------
extern "C" void kernel_launch(void* const* d_in, const int* in_sizes, int n_in,
                              void* d_out, int out_size) {
    const int*   ids = (const int*)d_in[0];     // (1024,120,1) int32
    const float* emb = (const float*)d_in[1];   // (50000,50)
    const float* W   = (const float*)d_in[2];   // (350,1200)
    const float* bl  = (const float*)d_in[3];   // (1200)
    const float* U   = (const float*)d_in[4];   // (300,5)
    const float* b2  = (const float*)d_in[5];   // (5)
    float* out = (float*)d_out;                 // (120,1024,5)

    cudaFuncSetAttribute(lstm_persist,
                         cudaFuncAttributeMaxDynamicSharedMemorySize, SMEM_STEP);
    cudaFuncSetAttribute(proj_kernel,
                         cudaFuncAttributeMaxDynamicSharedMemorySize, PROJ_SMEM);

    dim3 ewgrid((GATES + 63) / 64, (VOCAB + 63) / 64);
    ew_kernel<<<ewgrid, 256>>>(emb, W, bl);
    pack_b<<<(NTL * BN * BSTRIDE + 255) / 256, 256>>>(W);

    lstm_persist<<<NBLK, 256, SMEM_STEP>>>(ids);

    proj_kernel<<<(SEQ * BATCH) / PROJ_ROWS, 256, PROJ_SMEM>>>(U, b2, out);
}